// round 7
// baseline (speedup 1.0000x reference)
#include <cuda_runtime.h>
#include <cuda_fp16.h>
#include <cuda_fp8.h>

#define V 4096
#define T 4096
#define FW 5
#define BATCH 64
#define SLEN 512
#define NROWS (BATCH * SLEN)   // 32768
#define CDIM (V * FW)          // 20480
#define MARGIN 2.2e-2f
#define MAXC 32
#define WSCALE 64.0f
#define INVSCALE 0.015625f
#define TIE_EPS 4e-6f
#define ROWSPB 4

// fp8 (e4m3, x64-scaled) transposed weights W8[k][v][t] -- 84 MB, L2-resident
__device__ unsigned char g_W8[(size_t)FW * V * T];
__device__ float g_c0[NROWS];
__device__ float g_mp[NROWS];
__device__ int   g_cnt[NROWS];          // RAW candidate count (may exceed MAXC)
__device__ int   g_cand[NROWS][MAXC];
__device__ float g_rowent[NROWS];
__device__ int   g_flaglist[NROWS];
__device__ int   g_nflag;

// ---------------------------------------------------------------------------
// Kernel 1: transpose W[t][v][k] f32 -> W8[k][v][t] fp8(e4m3, x64)
// ---------------------------------------------------------------------------
__global__ __launch_bounds__(256) void transpose_k(const float* __restrict__ W) {
    __shared__ float tile[128][33];     // [t][c]
    int c0 = blockIdx.x << 5;
    int t0 = blockIdx.y << 7;
    int tx = threadIdx.x;
    int ty = threadIdx.y;

#pragma unroll
    for (int j = 0; j < 16; j++) {
        int r = j * 8 + ty;
        tile[r][tx] = W[(size_t)(t0 + r) * CDIM + c0 + tx];
    }
    __syncthreads();
#pragma unroll
    for (int j = 0; j < 4; j++) {
        int c = j * 8 + ty;
        int cc = c0 + c;
        int v = cc / 5;
        int k = cc - 5 * v;
        float f0 = tile[4 * tx + 0][c] * WSCALE;
        float f1 = tile[4 * tx + 1][c] * WSCALE;
        float f2 = tile[4 * tx + 2][c] * WSCALE;
        float f3 = tile[4 * tx + 3][c] * WSCALE;
        unsigned int lo = __nv_cvt_float2_to_fp8x2(make_float2(f0, f1), __NV_SATFINITE, __NV_E4M3);
        unsigned int hi = __nv_cvt_float2_to_fp8x2(make_float2(f2, f3), __NV_SATFINITE, __NV_E4M3);
        *(unsigned int*)(g_W8 + ((size_t)k * V + v) * T + t0 + 4 * tx) = lo | (hi << 16);
    }
}

// ---------------------------------------------------------------------------
// Kernel 2: fp8 gather, 4 rows/block, 16 t/thread. Emits mp, c0, rowent,
// raw candidate count + up to MAXC candidate indices (l >= mp - MARGIN).
// ---------------------------------------------------------------------------
__global__ __launch_bounds__(256, 2) void gather_k(const float* __restrict__ bias,
                                                   const int* __restrict__ sent) {
    int r0 = blockIdx.x * ROWSPB;
    int bb = r0 >> 9;
    int s0r = r0 & 511;
    int tid = threadIdx.x;
    int lane = tid & 31, warp = tid >> 5;
    int tb = tid * 16;

    __shared__ float red[8];
    __shared__ float red2[8];
    __shared__ float bc[2];
    __shared__ int scand[MAXC];
    __shared__ int scnt;

    float bs[16];
    {
        const float4* b4 = (const float4*)(bias + tb);
#pragma unroll
        for (int i = 0; i < 4; i++) {
            float4 t4 = b4[i];
            bs[4 * i + 0] = t4.x; bs[4 * i + 1] = t4.y;
            bs[4 * i + 2] = t4.z; bs[4 * i + 3] = t4.w;
        }
    }

    __half2 acc[ROWSPB][8];
    __half2 z2 = __float2half2_rn(0.f);
#pragma unroll
    for (int rr = 0; rr < ROWSPB; rr++)
#pragma unroll
        for (int j = 0; j < 8; j++) acc[rr][j] = z2;

#pragma unroll
    for (int k = 0; k < FW; k++) {
#pragma unroll
        for (int rr = 0; rr < ROWSPB; rr++) {
            int p = s0r + rr + k - 2;
            if (p >= 0 && p < SLEN) {
                int tok = __ldg(&sent[(bb << 9) + p]);
                uint4 w = *(const uint4*)(g_W8 + ((size_t)k * V + tok) * T + tb);
                const unsigned int* wu = (const unsigned int*)&w;
#pragma unroll
                for (int q = 0; q < 4; q++) {
                    __half2_raw h0 = __nv_cvt_fp8x2_to_halfraw2(
                        (__nv_fp8x2_storage_t)(wu[q] & 0xffffu), __NV_E4M3);
                    __half2_raw h1 = __nv_cvt_fp8x2_to_halfraw2(
                        (__nv_fp8x2_storage_t)(wu[q] >> 16), __NV_E4M3);
                    acc[rr][2 * q + 0] = __hadd2(acc[rr][2 * q + 0], *(__half2*)&h0);
                    acc[rr][2 * q + 1] = __hadd2(acc[rr][2 * q + 1], *(__half2*)&h1);
                }
            }
        }
    }

    for (int rr = 0; rr < ROWSPB; rr++) {
        int row = r0 + rr;

        float vmax = -1e30f;
        float lv[16];
#pragma unroll
        for (int j = 0; j < 8; j++) {
            float2 f = __half22float2(acc[rr][j]);
            float l0 = fmaf(f.x, INVSCALE, bs[2 * j + 0]);
            float l1 = fmaf(f.y, INVSCALE, bs[2 * j + 1]);
            lv[2 * j] = l0; lv[2 * j + 1] = l1;
            vmax = fmaxf(vmax, fmaxf(l0, l1));
        }
#pragma unroll
        for (int o = 16; o > 0; o >>= 1)
            vmax = fmaxf(vmax, __shfl_xor_sync(0xffffffffu, vmax, o));
        if (lane == 0) red[warp] = vmax;
        if (tid == 0) scnt = 0;
        __syncthreads();
        if (warp == 0) {
            float v = (lane < 8) ? red[lane] : -1e30f;
#pragma unroll
            for (int o = 4; o > 0; o >>= 1)
                v = fmaxf(v, __shfl_xor_sync(0xffffffffu, v, o));
            if (lane == 0) bc[0] = v;
        }
        __syncthreads();
        float mc = bc[0];

        float s0 = 0.f, s1 = 0.f;
        float thr = mc - MARGIN;
#pragma unroll
        for (int j = 0; j < 16; j++) {
            float d = lv[j] - mc;
            float e = __expf(d);
            s0 += e;
            s1 += d * e;
            if (lv[j] >= thr) {
                int idx = atomicAdd(&scnt, 1);
                if (idx < MAXC) scand[idx] = tb + j;
            }
        }
#pragma unroll
        for (int o = 16; o > 0; o >>= 1) {
            s0 += __shfl_xor_sync(0xffffffffu, s0, o);
            s1 += __shfl_xor_sync(0xffffffffu, s1, o);
        }
        if (lane == 0) { red[warp] = s0; red2[warp] = s1; }
        __syncthreads();
        if (warp == 0) {
            float a = (lane < 8) ? red[lane] : 0.f;
            float b = (lane < 8) ? red2[lane] : 0.f;
#pragma unroll
            for (int o = 4; o > 0; o >>= 1) {
                a += __shfl_xor_sync(0xffffffffu, a, o);
                b += __shfl_xor_sync(0xffffffffu, b, o);
            }
            if (lane == 0) { bc[0] = a; bc[1] = b; }
        }
        __syncthreads();

        int rawn = scnt;
        int nc = rawn < MAXC ? rawn : MAXC;
        if (tid < MAXC) g_cand[row][tid] = (tid < nc) ? scand[tid] : 0;
        if (tid == 0) {
            float S0 = bc[0], S1 = bc[1];
            float c0 = logf(S0);
            g_c0[row] = c0;
            g_mp[row] = mc;
            g_cnt[row] = rawn;             // RAW count (overflow detectable)
            g_rowent[row] = c0 - S1 / S0;
        }
        __syncthreads();
    }
}

// ---------------------------------------------------------------------------
__global__ void reset_k() { g_nflag = 0; }

__device__ __forceinline__ float exact_logit(const float* __restrict__ bias,
                                             const float* __restrict__ W,
                                             const int* toks, int t) {
    float l = __ldg(&bias[t]);
#pragma unroll
    for (int k = 0; k < FW; k++)
        if (toks[k] >= 0)
            l += __ldg(&W[(size_t)t * CDIM + toks[k] * 5 + k]);
    return l;
}

// ---------------------------------------------------------------------------
// Kernel 3: combine. 8 lanes/row; exact fp32 recheck of candidates. Rows
// with candidate overflow OR >=2 exact logits within TIE_EPS of the max
// go to the exact fixup list.
// ---------------------------------------------------------------------------
__global__ __launch_bounds__(256) void combine_k(const float* __restrict__ bias,
                                                 const int* __restrict__ sent,
                                                 const float* __restrict__ W,
                                                 float* __restrict__ out) {
    int tid = threadIdx.x;
    int row = blockIdx.x * 32 + (tid >> 3);
    int lane8 = tid & 7;
    int bb = row >> 9, s = row & 511;

    int rawn = g_cnt[row];
    int nc = rawn < MAXC ? rawn : MAXC;
    float mp = g_mp[row], c0 = g_c0[row];

    int toks[FW];
#pragma unroll
    for (int k = 0; k < FW; k++) {
        int p = s + k - 2;
        toks[k] = (p >= 0 && p < SLEN) ? __ldg(&sent[(bb << 9) + p]) : -1;
    }

    // each lane handles candidates lane8, lane8+8, lane8+16, lane8+24
    float le[4]; int te[4];
#pragma unroll
    for (int i = 0; i < 4; i++) {
        int ci = lane8 + 8 * i;
        if (ci < nc) { te[i] = g_cand[row][ci]; le[i] = exact_logit(bias, W, toks, te[i]); }
        else         { te[i] = 0x7fffffff;      le[i] = -1e30f; }
    }

    float m = fmaxf(fmaxf(le[0], le[1]), fmaxf(le[2], le[3]));
#pragma unroll
    for (int o = 4; o > 0; o >>= 1)
        m = fmaxf(m, __shfl_xor_sync(0xffffffffu, m, o, 8));
    float cc = c0 + (mp - m);

    float blp = -1e30f; int bt = 0x7fffffff;
    int near = 0;
#pragma unroll
    for (int i = 0; i < 4; i++) {
        if (te[i] != 0x7fffffff) {
            float lp = (le[i] - m) - cc;
            if (lp > blp || (lp == blp && te[i] < bt)) { blp = lp; bt = te[i]; }
            if (le[i] > m - TIE_EPS) near++;
        }
    }
#pragma unroll
    for (int o = 4; o > 0; o >>= 1) {
        float olp = __shfl_xor_sync(0xffffffffu, blp, o, 8);
        int   ot  = __shfl_xor_sync(0xffffffffu, bt,  o, 8);
        int   on  = __shfl_xor_sync(0xffffffffu, near, o, 8);
        if (olp > blp || (olp == blp && ot < bt)) { blp = olp; bt = ot; }
        near += on;
    }

    if (lane8 == 0) {
        out[row] = (float)bt;
        out[NROWS + row] = blp;
        if (near >= 2 || rawn > MAXC) {
            int ix = atomicAdd(&g_nflag, 1);
            g_flaglist[ix] = row;
        }
    }
}

// ---------------------------------------------------------------------------
// Kernel 4: exact fixup for flagged rows: all 4096 fp32 logits, accurate
// exp/log, quantized-lp argmax with first-index ties (R2-proven recipe).
// ---------------------------------------------------------------------------
__global__ __launch_bounds__(256) void fixup_k(const float* __restrict__ bias,
                                               const int* __restrict__ sent,
                                               const float* __restrict__ W,
                                               float* __restrict__ out) {
    __shared__ float sv[256];
    __shared__ int   si[256];
    __shared__ float sb[1];
    int tid = threadIdx.x;
    int nf = g_nflag;

    for (int it = blockIdx.x; it < nf; it += gridDim.x) {
        int row = g_flaglist[it];
        int bb = row >> 9, s = row & 511;
        int toks[FW];
#pragma unroll
        for (int k = 0; k < FW; k++) {
            int p = s + k - 2;
            toks[k] = (p >= 0 && p < SLEN) ? __ldg(&sent[(bb << 9) + p]) : -1;
        }
        float lv[16];
        float vmax = -1e30f;
#pragma unroll
        for (int j = 0; j < 16; j++) {
            lv[j] = exact_logit(bias, W, toks, tid * 16 + j);
            vmax = fmaxf(vmax, lv[j]);
        }
        sv[tid] = vmax;
        __syncthreads();
#pragma unroll
        for (int off = 128; off > 0; off >>= 1) {
            if (tid < off) sv[tid] = fmaxf(sv[tid], sv[tid + off]);
            __syncthreads();
        }
        float m = sv[0];
        __syncthreads();

        float s0 = 0.f;
#pragma unroll
        for (int j = 0; j < 16; j++) s0 += expf(lv[j] - m);
        sv[tid] = s0;
        __syncthreads();
#pragma unroll
        for (int off = 128; off > 0; off >>= 1) {
            if (tid < off) sv[tid] += sv[tid + off];
            __syncthreads();
        }
        if (tid == 0) sb[0] = logf(sv[0]);
        __syncthreads();
        float c = sb[0];
        __syncthreads();

        float blp = -1e30f;
        int bt = 0;
#pragma unroll
        for (int j = 0; j < 16; j++) {
            float lp = (lv[j] - m) - c;
            if (lp > blp) { blp = lp; bt = tid * 16 + j; }
        }
        sv[tid] = blp; si[tid] = bt;
        __syncthreads();
#pragma unroll
        for (int off = 128; off > 0; off >>= 1) {
            if (tid < off) {
                float ov = sv[tid + off];
                int   oi = si[tid + off];
                if (ov > sv[tid] || (ov == sv[tid] && oi < si[tid])) {
                    sv[tid] = ov; si[tid] = oi;
                }
            }
            __syncthreads();
        }
        if (tid == 0) {
            out[row] = (float)si[0];
            out[NROWS + row] = sv[0];
        }
        __syncthreads();
    }
}

// ---------------------------------------------------------------------------
__global__ __launch_bounds__(256) void finalize_k(float* __restrict__ out) {
    __shared__ double sd[256];
    int tid = threadIdx.x;
    double a = 0.0;
    for (int i = tid; i < NROWS; i += 256) a += (double)g_rowent[i];
    sd[tid] = a;
    __syncthreads();
#pragma unroll
    for (int off = 128; off > 0; off >>= 1) {
        if (tid < off) sd[tid] += sd[tid + off];
        __syncthreads();
    }
    if (tid == 0)
        out[2 * NROWS] = (float)(sd[0] / ((double)NROWS * (double)T));
}

// ---------------------------------------------------------------------------
extern "C" void kernel_launch(void* const* d_in, const int* in_sizes, int n_in,
                              void* d_out, int out_size) {
    const float* W    = (const float*)d_in[0];
    const float* bias = (const float*)d_in[1];
    const int*   sent = (const int*)d_in[2];
    float* out = (float*)d_out;

    dim3 tb(32, 8);
    dim3 tg(CDIM / 32, T / 128);
    transpose_k<<<tg, tb>>>(W);
    gather_k<<<NROWS / ROWSPB, 256>>>(bias, sent);
    reset_k<<<1, 1>>>();
    combine_k<<<NROWS / 32, 256>>>(bias, sent, W, out);
    fixup_k<<<128, 256>>>(bias, sent, W, out);
    finalize_k<<<1, 256>>>(out);
}

// round 8
// speedup vs baseline: 11.8361x; 11.8361x over previous
#include <cuda_runtime.h>

#define V 4096
#define T 4096
#define FW 5
#define BATCH 64
#define SLEN 512
#define NROWS (BATCH * SLEN)   // 32768
#define CDIM (V * FW)          // 20480
#define MARGIN 1.2e-3f
#define MAXC 16
#define TIE_EPS 4e-6f
#define ROWSPB 2
#define NTB 32                 // t-blocks of 128

// int8 transposed weights W8[k][v][t] -- 84 MB (L2-resident working set)
__device__ signed char g_W8[(size_t)FW * V * T];
// per-(k,v,tblock) dequant scale
__device__ float g_scale[FW * V * NTB];
__device__ float g_c0[NROWS];
__device__ float g_mp[NROWS];
__device__ int   g_cnt[NROWS];          // RAW candidate count
__device__ int   g_cand[NROWS][MAXC];
__device__ float g_rowent[NROWS];
__device__ int   g_flaglist[NROWS];
__device__ int   g_nflag;

// ---------------------------------------------------------------------------
// Kernel 1: transpose W[t][v][k] f32 -> W8[k][v][t] int8 with per-(c,tblock)
// scale (maxabs over the 128-t tile / 127). grid (CDIM/32, T/128), block(32,8)
// ---------------------------------------------------------------------------
__global__ __launch_bounds__(256) void transpose_k(const float* __restrict__ W) {
    __shared__ float tile[128][33];     // [t][c]
    __shared__ float smax[8][32];
    __shared__ float sinv[32];
    int c0 = blockIdx.x << 5;
    int tb = blockIdx.y;
    int t0 = tb << 7;
    int tx = threadIdx.x;
    int ty = threadIdx.y;

#pragma unroll
    for (int j = 0; j < 16; j++) {
        int r = j * 8 + ty;
        tile[r][tx] = W[(size_t)(t0 + r) * CDIM + c0 + tx];
    }
    __syncthreads();

    // per-c maxabs over 128 t
    float mx = 0.f;
#pragma unroll
    for (int i = 0; i < 16; i++) mx = fmaxf(mx, fabsf(tile[ty * 16 + i][tx]));
    smax[ty][tx] = mx;
    __syncthreads();
    if (ty == 0) {
        float m = smax[0][tx];
#pragma unroll
        for (int g = 1; g < 8; g++) m = fmaxf(m, smax[g][tx]);
        sinv[tx] = (m > 0.f) ? 127.0f / m : 0.f;
        int cc = c0 + tx;
        int v = cc / 5;
        int k = cc - 5 * v;
        g_scale[((k * V + v) << 5) + tb] = m * (1.0f / 127.0f);
    }
    __syncthreads();

#pragma unroll
    for (int j = 0; j < 4; j++) {
        int c = j * 8 + ty;
        int cc = c0 + c;
        int v = cc / 5;
        int k = cc - 5 * v;
        float inv = sinv[c];
        int q0 = __float2int_rn(tile[4 * tx + 0][c] * inv);
        int q1 = __float2int_rn(tile[4 * tx + 1][c] * inv);
        int q2 = __float2int_rn(tile[4 * tx + 2][c] * inv);
        int q3 = __float2int_rn(tile[4 * tx + 3][c] * inv);
        unsigned int pk = (q0 & 0xff) | ((q1 & 0xff) << 8) |
                          ((q2 & 0xff) << 16) | ((unsigned int)(q3 & 0xff) << 24);
        *(unsigned int*)(g_W8 + ((size_t)k * V + v) * T + t0 + 4 * tx) = pk;
    }
}

// ---------------------------------------------------------------------------
// Kernel 2: int8 gather, 2 rows/block, 16 t/thread, fp32 accumulation.
// Emits mp, c0, rowent, raw candidate count + candidates (l >= mp - MARGIN).
// ---------------------------------------------------------------------------
__global__ __launch_bounds__(256, 3) void gather_k(const float* __restrict__ bias,
                                                   const int* __restrict__ sent) {
    int r0 = blockIdx.x * ROWSPB;
    int bb = r0 >> 9;
    int s0r = r0 & 511;
    int tid = threadIdx.x;
    int lane = tid & 31, warp = tid >> 5;
    int tb16 = tid * 16;
    int tblk = tid >> 3;    // (tid*16)/128

    __shared__ float red[8];
    __shared__ float red2[8];
    __shared__ float bc[2];
    __shared__ int scand[MAXC];
    __shared__ int scnt;

    float acc[ROWSPB][16];
    {
        const float4* b4 = (const float4*)(bias + tb16);
#pragma unroll
        for (int i = 0; i < 4; i++) {
            float4 t4 = b4[i];
            acc[0][4 * i + 0] = t4.x; acc[0][4 * i + 1] = t4.y;
            acc[0][4 * i + 2] = t4.z; acc[0][4 * i + 3] = t4.w;
        }
#pragma unroll
        for (int i = 0; i < 16; i++) acc[1][i] = acc[0][i];
    }

#pragma unroll
    for (int k = 0; k < FW; k++) {
#pragma unroll
        for (int rr = 0; rr < ROWSPB; rr++) {
            int p = s0r + rr + k - 2;
            if (p >= 0 && p < SLEN) {
                int tok = __ldg(&sent[(bb << 9) + p]);
                float sc = __ldg(&g_scale[((k * V + tok) << 5) + tblk]);
                uint4 w = *(const uint4*)(g_W8 + ((size_t)k * V + tok) * T + tb16);
                const unsigned int* wu = (const unsigned int*)&w;
#pragma unroll
                for (int q = 0; q < 4; q++) {
                    unsigned int u = wu[q];
                    acc[rr][4 * q + 0] = fmaf((float)(int)(signed char)(u),       sc, acc[rr][4 * q + 0]);
                    acc[rr][4 * q + 1] = fmaf((float)(int)(signed char)(u >> 8),  sc, acc[rr][4 * q + 1]);
                    acc[rr][4 * q + 2] = fmaf((float)(int)(signed char)(u >> 16), sc, acc[rr][4 * q + 2]);
                    acc[rr][4 * q + 3] = fmaf((float)(int)(signed char)(u >> 24), sc, acc[rr][4 * q + 3]);
                }
            }
        }
    }

    for (int rr = 0; rr < ROWSPB; rr++) {
        int row = r0 + rr;

        float vmax = acc[rr][0];
#pragma unroll
        for (int j = 1; j < 16; j++) vmax = fmaxf(vmax, acc[rr][j]);
#pragma unroll
        for (int o = 16; o > 0; o >>= 1)
            vmax = fmaxf(vmax, __shfl_xor_sync(0xffffffffu, vmax, o));
        if (lane == 0) red[warp] = vmax;
        if (tid == 0) scnt = 0;
        __syncthreads();
        if (warp == 0) {
            float v = (lane < 8) ? red[lane] : -1e30f;
#pragma unroll
            for (int o = 4; o > 0; o >>= 1)
                v = fmaxf(v, __shfl_xor_sync(0xffffffffu, v, o));
            if (lane == 0) bc[0] = v;
        }
        __syncthreads();
        float mc = bc[0];

        float s0 = 0.f, s1 = 0.f;
        float thr = mc - MARGIN;
#pragma unroll
        for (int j = 0; j < 16; j++) {
            float d = acc[rr][j] - mc;
            float e = __expf(d);
            s0 += e;
            s1 += d * e;
            if (acc[rr][j] >= thr) {
                int idx = atomicAdd(&scnt, 1);
                if (idx < MAXC) scand[idx] = tb16 + j;
            }
        }
#pragma unroll
        for (int o = 16; o > 0; o >>= 1) {
            s0 += __shfl_xor_sync(0xffffffffu, s0, o);
            s1 += __shfl_xor_sync(0xffffffffu, s1, o);
        }
        if (lane == 0) { red[warp] = s0; red2[warp] = s1; }
        __syncthreads();
        if (warp == 0) {
            float a = (lane < 8) ? red[lane] : 0.f;
            float b = (lane < 8) ? red2[lane] : 0.f;
#pragma unroll
            for (int o = 4; o > 0; o >>= 1) {
                a += __shfl_xor_sync(0xffffffffu, a, o);
                b += __shfl_xor_sync(0xffffffffu, b, o);
            }
            if (lane == 0) { bc[0] = a; bc[1] = b; }
        }
        __syncthreads();

        int rawn = scnt;
        int nc = rawn < MAXC ? rawn : MAXC;
        if (tid < MAXC) g_cand[row][tid] = (tid < nc) ? scand[tid] : 0;
        if (tid == 0) {
            float S0 = bc[0], S1 = bc[1];
            float c0 = logf(S0);
            g_c0[row] = c0;
            g_mp[row] = mc;
            g_cnt[row] = rawn;
            g_rowent[row] = c0 - S1 / S0;
        }
        __syncthreads();
    }
}

// ---------------------------------------------------------------------------
__global__ void reset_k() { g_nflag = 0; }

__device__ __forceinline__ float exact_logit(const float* __restrict__ bias,
                                             const float* __restrict__ W,
                                             const int* toks, int t) {
    float l = __ldg(&bias[t]);
#pragma unroll
    for (int k = 0; k < FW; k++)
        if (toks[k] >= 0)
            l += __ldg(&W[(size_t)t * CDIM + toks[k] * 5 + k]);
    return l;
}

// ---------------------------------------------------------------------------
// Kernel 3: combine. 8 lanes/row; exact fp32 recheck of candidates.
// Flags rows with overflow or >=2 exact logits within TIE_EPS of max.
// ---------------------------------------------------------------------------
__global__ __launch_bounds__(256) void combine_k(const float* __restrict__ bias,
                                                 const int* __restrict__ sent,
                                                 const float* __restrict__ W,
                                                 float* __restrict__ out) {
    int tid = threadIdx.x;
    int row = blockIdx.x * 32 + (tid >> 3);
    int lane8 = tid & 7;
    int bb = row >> 9, s = row & 511;

    int rawn = g_cnt[row];
    int nc = rawn < MAXC ? rawn : MAXC;
    float mp = g_mp[row], c0 = g_c0[row];

    int toks[FW];
#pragma unroll
    for (int k = 0; k < FW; k++) {
        int p = s + k - 2;
        toks[k] = (p >= 0 && p < SLEN) ? __ldg(&sent[(bb << 9) + p]) : -1;
    }

    float le[2]; int te[2];
#pragma unroll
    for (int i = 0; i < 2; i++) {
        int ci = lane8 + 8 * i;
        if (ci < nc) { te[i] = g_cand[row][ci]; le[i] = exact_logit(bias, W, toks, te[i]); }
        else         { te[i] = 0x7fffffff;      le[i] = -1e30f; }
    }

    float m = fmaxf(le[0], le[1]);
#pragma unroll
    for (int o = 4; o > 0; o >>= 1)
        m = fmaxf(m, __shfl_xor_sync(0xffffffffu, m, o, 8));
    float cc = c0 + (mp - m);

    float blp = -1e30f; int bt = 0x7fffffff;
    int near = 0;
#pragma unroll
    for (int i = 0; i < 2; i++) {
        if (te[i] != 0x7fffffff) {
            float lp = (le[i] - m) - cc;
            if (lp > blp || (lp == blp && te[i] < bt)) { blp = lp; bt = te[i]; }
            if (le[i] > m - TIE_EPS) near++;
        }
    }
#pragma unroll
    for (int o = 4; o > 0; o >>= 1) {
        float olp = __shfl_xor_sync(0xffffffffu, blp, o, 8);
        int   ot  = __shfl_xor_sync(0xffffffffu, bt,  o, 8);
        int   on  = __shfl_xor_sync(0xffffffffu, near, o, 8);
        if (olp > blp || (olp == blp && ot < bt)) { blp = olp; bt = ot; }
        near += on;
    }

    if (lane8 == 0) {
        out[row] = (float)bt;
        out[NROWS + row] = blp;
        if (near >= 2 || rawn > MAXC) {
            int ix = atomicAdd(&g_nflag, 1);
            g_flaglist[ix] = row;
        }
    }
}

// ---------------------------------------------------------------------------
// Kernel 4: exact fixup for flagged rows (full 4096 fp32 logits, accurate
// exp/log, quantized-lp argmax with first-index ties).
// ---------------------------------------------------------------------------
__global__ __launch_bounds__(256) void fixup_k(const float* __restrict__ bias,
                                               const int* __restrict__ sent,
                                               const float* __restrict__ W,
                                               float* __restrict__ out) {
    __shared__ float sv[256];
    __shared__ int   si[256];
    __shared__ float sb[1];
    int tid = threadIdx.x;
    int nf = g_nflag;

    for (int it = blockIdx.x; it < nf; it += gridDim.x) {
        int row = g_flaglist[it];
        int bb = row >> 9, s = row & 511;
        int toks[FW];
#pragma unroll
        for (int k = 0; k < FW; k++) {
            int p = s + k - 2;
            toks[k] = (p >= 0 && p < SLEN) ? __ldg(&sent[(bb << 9) + p]) : -1;
        }
        float lv[16];
        float vmax = -1e30f;
#pragma unroll
        for (int j = 0; j < 16; j++) {
            lv[j] = exact_logit(bias, W, toks, tid * 16 + j);
            vmax = fmaxf(vmax, lv[j]);
        }
        sv[tid] = vmax;
        __syncthreads();
#pragma unroll
        for (int off = 128; off > 0; off >>= 1) {
            if (tid < off) sv[tid] = fmaxf(sv[tid], sv[tid + off]);
            __syncthreads();
        }
        float m = sv[0];
        __syncthreads();

        float s0 = 0.f;
#pragma unroll
        for (int j = 0; j < 16; j++) s0 += expf(lv[j] - m);
        sv[tid] = s0;
        __syncthreads();
#pragma unroll
        for (int off = 128; off > 0; off >>= 1) {
            if (tid < off) sv[tid] += sv[tid + off];
            __syncthreads();
        }
        if (tid == 0) sb[0] = logf(sv[0]);
        __syncthreads();
        float c = sb[0];
        __syncthreads();

        float blp = -1e30f;
        int bt = 0;
#pragma unroll
        for (int j = 0; j < 16; j++) {
            float lp = (lv[j] - m) - c;
            if (lp > blp) { blp = lp; bt = tid * 16 + j; }
        }
        sv[tid] = blp; si[tid] = bt;
        __syncthreads();
#pragma unroll
        for (int off = 128; off > 0; off >>= 1) {
            if (tid < off) {
                float ov = sv[tid + off];
                int   oi = si[tid + off];
                if (ov > sv[tid] || (ov == sv[tid] && oi < si[tid])) {
                    sv[tid] = ov; si[tid] = oi;
                }
            }
            __syncthreads();
        }
        if (tid == 0) {
            out[row] = (float)si[0];
            out[NROWS + row] = sv[0];
        }
        __syncthreads();
    }
}

// ---------------------------------------------------------------------------
__global__ __launch_bounds__(256) void finalize_k(float* __restrict__ out) {
    __shared__ double sd[256];
    int tid = threadIdx.x;
    double a = 0.0;
    for (int i = tid; i < NROWS; i += 256) a += (double)g_rowent[i];
    sd[tid] = a;
    __syncthreads();
#pragma unroll
    for (int off = 128; off > 0; off >>= 1) {
        if (tid < off) sd[tid] += sd[tid + off];
        __syncthreads();
    }
    if (tid == 0)
        out[2 * NROWS] = (float)(sd[0] / ((double)NROWS * (double)T));
}

// ---------------------------------------------------------------------------
extern "C" void kernel_launch(void* const* d_in, const int* in_sizes, int n_in,
                              void* d_out, int out_size) {
    const float* W    = (const float*)d_in[0];
    const float* bias = (const float*)d_in[1];
    const int*   sent = (const int*)d_in[2];
    float* out = (float*)d_out;

    dim3 tb(32, 8);
    dim3 tg(CDIM / 32, T / 128);
    transpose_k<<<tg, tb>>>(W);
    gather_k<<<NROWS / ROWSPB, 256>>>(bias, sent);
    reset_k<<<1, 1>>>();
    combine_k<<<NROWS / 32, 256>>>(bias, sent, W, out);
    fixup_k<<<128, 256>>>(bias, sent, W, out);
    finalize_k<<<1, 256>>>(out);
}

// round 9
// speedup vs baseline: 11.9144x; 1.0066x over previous
#include <cuda_runtime.h>

#define V 4096
#define T 4096
#define FW 5
#define BATCH 64
#define SLEN 512
#define NROWS (BATCH * SLEN)   // 32768
#define CDIM (V * FW)          // 20480
#define WMAX 0.06f
#define INVQ (127.0f / WMAX)
#define QUANT (WMAX / 127.0f)
#define MARGIN 2.5e-3f
#define MAXC 16
#define TIE_EPS 4e-6f
#define ROWSPB 4

// int8 transposed weights W8[k][v][t] -- 84 MB working set
__device__ signed char g_W8[(size_t)FW * V * T];
__device__ float g_c0[NROWS];
__device__ float g_mp[NROWS];
__device__ int   g_cnt[NROWS];
__device__ int   g_cand[NROWS][MAXC];
__device__ float g_rowent[NROWS];
__device__ int   g_flaglist[NROWS];
__device__ int   g_nflag;
__device__ int   g_clamped;

// ---------------------------------------------------------------------------
__global__ void reset_k() { g_nflag = 0; g_clamped = 0; }

// ---------------------------------------------------------------------------
// Kernel 1: transpose W[t][v][k] f32 -> W8[k][v][t] int8, FIXED global scale.
// grid (CDIM/32, T/128), block (32,8)
// ---------------------------------------------------------------------------
__global__ __launch_bounds__(256) void transpose_k(const float* __restrict__ W) {
    __shared__ float tile[128][33];     // [t][c]
    int c0 = blockIdx.x << 5;
    int t0 = blockIdx.y << 7;
    int tx = threadIdx.x;
    int ty = threadIdx.y;

#pragma unroll
    for (int j = 0; j < 16; j++) {
        int r = j * 8 + ty;
        tile[r][tx] = W[(size_t)(t0 + r) * CDIM + c0 + tx];
    }
    __syncthreads();

    bool clamp = false;
#pragma unroll
    for (int j = 0; j < 4; j++) {
        int c = j * 8 + ty;
        int cc = c0 + c;
        int v = cc / 5;
        int k = cc - 5 * v;
        int q[4];
#pragma unroll
        for (int i = 0; i < 4; i++) {
            float w = tile[4 * tx + i][c];
            int qi = __float2int_rn(w * INVQ);
            if (qi > 127) { qi = 127; clamp = true; }
            if (qi < -127) { qi = -127; clamp = true; }
            q[i] = qi;
        }
        unsigned int pk = (q[0] & 0xff) | ((q[1] & 0xff) << 8) |
                          ((q[2] & 0xff) << 16) | ((unsigned int)(q[3] & 0xff) << 24);
        *(unsigned int*)(g_W8 + ((size_t)k * V + v) * T + t0 + 4 * tx) = pk;
    }
    if (clamp) atomicExch(&g_clamped, 1);
}

// ---------------------------------------------------------------------------
// Kernel 2: int8 gather, 4 rows/block, 16 t/thread. u16-lane integer
// accumulation (XOR 0x80 excess-128 + PRMT expand + IADD), single I2F+FMA
// per t at epilogue. Emits mp, c0, rowent, candidates (l >= mp - MARGIN).
// ---------------------------------------------------------------------------
__global__ __launch_bounds__(256, 3) void gather_k(const float* __restrict__ bias,
                                                   const int* __restrict__ sent) {
    int r0 = blockIdx.x * ROWSPB;
    int bb = r0 >> 9;
    int s0r = r0 & 511;
    int tid = threadIdx.x;
    int lane = tid & 31, warp = tid >> 5;
    int tb16 = tid * 16;

    __shared__ float red[8];
    __shared__ float red2[8];
    __shared__ float bc[2];
    __shared__ int scand[MAXC];
    __shared__ int scnt;

    float bs[16];
    {
        const float4* b4 = (const float4*)(bias + tb16);
#pragma unroll
        for (int i = 0; i < 4; i++) {
            float4 t4 = b4[i];
            bs[4 * i + 0] = t4.x; bs[4 * i + 1] = t4.y;
            bs[4 * i + 2] = t4.z; bs[4 * i + 3] = t4.w;
        }
    }

    unsigned int acc[ROWSPB][8];   // u16 lanes: acc[rr][2q+h] holds t=4q+2h,4q+2h+1
#pragma unroll
    for (int rr = 0; rr < ROWSPB; rr++)
#pragma unroll
        for (int j = 0; j < 8; j++) acc[rr][j] = 0;
    int nvalid[ROWSPB];
#pragma unroll
    for (int rr = 0; rr < ROWSPB; rr++) nvalid[rr] = 0;

#pragma unroll
    for (int k = 0; k < FW; k++) {
#pragma unroll
        for (int rr = 0; rr < ROWSPB; rr++) {
            int p = s0r + rr + k - 2;
            if (p >= 0 && p < SLEN) {
                nvalid[rr]++;
                int tok = __ldg(&sent[(bb << 9) + p]);
                uint4 w = *(const uint4*)(g_W8 + ((size_t)k * V + tok) * T + tb16);
                const unsigned int* wu = (const unsigned int*)&w;
#pragma unroll
                for (int q = 0; q < 4; q++) {
                    unsigned int u = wu[q] ^ 0x80808080u;
                    acc[rr][2 * q + 0] += __byte_perm(u, 0, 0x4140);  // {b0,0,b1,0}
                    acc[rr][2 * q + 1] += __byte_perm(u, 0, 0x4342);  // {b2,0,b3,0}
                }
            }
        }
    }

    for (int rr = 0; rr < ROWSPB; rr++) {
        int row = r0 + rr;
        int off = 128 * nvalid[rr];

        // dequant logits
        float lv[16];
#pragma unroll
        for (int q = 0; q < 8; q++) {
            int lo = (int)(acc[rr][q] & 0xffffu) - off;
            int hi = (int)(acc[rr][q] >> 16) - off;
            lv[2 * q + 0] = fmaf((float)lo, QUANT, bs[2 * q + 0]);
            lv[2 * q + 1] = fmaf((float)hi, QUANT, bs[2 * q + 1]);
        }

        float vmax = lv[0];
#pragma unroll
        for (int j = 1; j < 16; j++) vmax = fmaxf(vmax, lv[j]);
#pragma unroll
        for (int o = 16; o > 0; o >>= 1)
            vmax = fmaxf(vmax, __shfl_xor_sync(0xffffffffu, vmax, o));
        if (lane == 0) red[warp] = vmax;
        if (tid == 0) scnt = 0;
        __syncthreads();
        if (warp == 0) {
            float v = (lane < 8) ? red[lane] : -1e30f;
#pragma unroll
            for (int o = 4; o > 0; o >>= 1)
                v = fmaxf(v, __shfl_xor_sync(0xffffffffu, v, o));
            if (lane == 0) bc[0] = v;
        }
        __syncthreads();
        float mc = bc[0];

        float s0 = 0.f, s1 = 0.f;
        float thr = mc - MARGIN;
#pragma unroll
        for (int j = 0; j < 16; j++) {
            float d = lv[j] - mc;
            float e = __expf(d);
            s0 += e;
            s1 += d * e;
            if (lv[j] >= thr) {
                int idx = atomicAdd(&scnt, 1);
                if (idx < MAXC) scand[idx] = tb16 + j;
            }
        }
#pragma unroll
        for (int o = 16; o > 0; o >>= 1) {
            s0 += __shfl_xor_sync(0xffffffffu, s0, o);
            s1 += __shfl_xor_sync(0xffffffffu, s1, o);
        }
        if (lane == 0) { red[warp] = s0; red2[warp] = s1; }
        __syncthreads();
        if (warp == 0) {
            float a = (lane < 8) ? red[lane] : 0.f;
            float b = (lane < 8) ? red2[lane] : 0.f;
#pragma unroll
            for (int o = 4; o > 0; o >>= 1) {
                a += __shfl_xor_sync(0xffffffffu, a, o);
                b += __shfl_xor_sync(0xffffffffu, b, o);
            }
            if (lane == 0) { bc[0] = a; bc[1] = b; }
        }
        __syncthreads();

        int rawn = scnt;
        int nc = rawn < MAXC ? rawn : MAXC;
        if (tid < MAXC) g_cand[row][tid] = (tid < nc) ? scand[tid] : 0;
        if (tid == 0) {
            float S0 = bc[0], S1 = bc[1];
            float c0 = logf(S0);
            g_c0[row] = c0;
            g_mp[row] = mc;
            g_cnt[row] = rawn;
            g_rowent[row] = c0 - S1 / S0;
        }
        __syncthreads();
    }
}

// ---------------------------------------------------------------------------
__device__ __forceinline__ float exact_logit(const float* __restrict__ bias,
                                             const float* __restrict__ W,
                                             const int* toks, int t) {
    float l = __ldg(&bias[t]);
#pragma unroll
    for (int k = 0; k < FW; k++)
        if (toks[k] >= 0)
            l += __ldg(&W[(size_t)t * CDIM + toks[k] * 5 + k]);
    return l;
}

// ---------------------------------------------------------------------------
// Kernel 3: combine. 8 lanes/row; exact fp32 recheck of candidates.
// Flags rows with overflow / near-ties / any clamped weight.
// ---------------------------------------------------------------------------
__global__ __launch_bounds__(256) void combine_k(const float* __restrict__ bias,
                                                 const int* __restrict__ sent,
                                                 const float* __restrict__ W,
                                                 float* __restrict__ out) {
    int tid = threadIdx.x;
    int row = blockIdx.x * 32 + (tid >> 3);
    int lane8 = tid & 7;
    int bb = row >> 9, s = row & 511;

    int rawn = g_cnt[row];
    int nc = rawn < MAXC ? rawn : MAXC;
    float mp = g_mp[row], c0 = g_c0[row];
    int clamped = g_clamped;

    int toks[FW];
#pragma unroll
    for (int k = 0; k < FW; k++) {
        int p = s + k - 2;
        toks[k] = (p >= 0 && p < SLEN) ? __ldg(&sent[(bb << 9) + p]) : -1;
    }

    float le[2]; int te[2];
#pragma unroll
    for (int i = 0; i < 2; i++) {
        int ci = lane8 + 8 * i;
        if (ci < nc) { te[i] = g_cand[row][ci]; le[i] = exact_logit(bias, W, toks, te[i]); }
        else         { te[i] = 0x7fffffff;      le[i] = -1e30f; }
    }

    float m = fmaxf(le[0], le[1]);
#pragma unroll
    for (int o = 4; o > 0; o >>= 1)
        m = fmaxf(m, __shfl_xor_sync(0xffffffffu, m, o, 8));
    float cc = c0 + (mp - m);

    float blp = -1e30f; int bt = 0x7fffffff;
    int near = 0;
#pragma unroll
    for (int i = 0; i < 2; i++) {
        if (te[i] != 0x7fffffff) {
            float lp = (le[i] - m) - cc;
            if (lp > blp || (lp == blp && te[i] < bt)) { blp = lp; bt = te[i]; }
            if (le[i] > m - TIE_EPS) near++;
        }
    }
#pragma unroll
    for (int o = 4; o > 0; o >>= 1) {
        float olp = __shfl_xor_sync(0xffffffffu, blp, o, 8);
        int   ot  = __shfl_xor_sync(0xffffffffu, bt,  o, 8);
        int   on  = __shfl_xor_sync(0xffffffffu, near, o, 8);
        if (olp > blp || (olp == blp && ot < bt)) { blp = olp; bt = ot; }
        near += on;
    }

    if (lane8 == 0) {
        out[row] = (float)bt;
        out[NROWS + row] = blp;
        if (near >= 2 || rawn > MAXC || clamped) {
            int ix = atomicAdd(&g_nflag, 1);
            g_flaglist[ix] = row;
        }
    }
}

// ---------------------------------------------------------------------------
// Kernel 4: exact fixup for flagged rows (full 4096 fp32 logits).
// ---------------------------------------------------------------------------
__global__ __launch_bounds__(256) void fixup_k(const float* __restrict__ bias,
                                               const int* __restrict__ sent,
                                               const float* __restrict__ W,
                                               float* __restrict__ out) {
    __shared__ float sv[256];
    __shared__ int   si[256];
    __shared__ float sb[1];
    int tid = threadIdx.x;
    int nf = g_nflag;

    for (int it = blockIdx.x; it < nf; it += gridDim.x) {
        int row = g_flaglist[it];
        int bb = row >> 9, s = row & 511;
        int toks[FW];
#pragma unroll
        for (int k = 0; k < FW; k++) {
            int p = s + k - 2;
            toks[k] = (p >= 0 && p < SLEN) ? __ldg(&sent[(bb << 9) + p]) : -1;
        }
        float lv[16];
        float vmax = -1e30f;
#pragma unroll
        for (int j = 0; j < 16; j++) {
            lv[j] = exact_logit(bias, W, toks, tid * 16 + j);
            vmax = fmaxf(vmax, lv[j]);
        }
        sv[tid] = vmax;
        __syncthreads();
#pragma unroll
        for (int off = 128; off > 0; off >>= 1) {
            if (tid < off) sv[tid] = fmaxf(sv[tid], sv[tid + off]);
            __syncthreads();
        }
        float m = sv[0];
        __syncthreads();

        float s0 = 0.f;
#pragma unroll
        for (int j = 0; j < 16; j++) s0 += expf(lv[j] - m);
        sv[tid] = s0;
        __syncthreads();
#pragma unroll
        for (int off = 128; off > 0; off >>= 1) {
            if (tid < off) sv[tid] += sv[tid + off];
            __syncthreads();
        }
        if (tid == 0) sb[0] = logf(sv[0]);
        __syncthreads();
        float c = sb[0];
        __syncthreads();

        float blp = -1e30f;
        int bt = 0;
#pragma unroll
        for (int j = 0; j < 16; j++) {
            float lp = (lv[j] - m) - c;
            if (lp > blp) { blp = lp; bt = tid * 16 + j; }
        }
        sv[tid] = blp; si[tid] = bt;
        __syncthreads();
#pragma unroll
        for (int off = 128; off > 0; off >>= 1) {
            if (tid < off) {
                float ov = sv[tid + off];
                int   oi = si[tid + off];
                if (ov > sv[tid] || (ov == sv[tid] && oi < si[tid])) {
                    sv[tid] = ov; si[tid] = oi;
                }
            }
            __syncthreads();
        }
        if (tid == 0) {
            out[row] = (float)si[0];
            out[NROWS + row] = sv[0];
        }
        __syncthreads();
    }
}

// ---------------------------------------------------------------------------
__global__ __launch_bounds__(256) void finalize_k(float* __restrict__ out) {
    __shared__ double sd[256];
    int tid = threadIdx.x;
    double a = 0.0;
    for (int i = tid; i < NROWS; i += 256) a += (double)g_rowent[i];
    sd[tid] = a;
    __syncthreads();
#pragma unroll
    for (int off = 128; off > 0; off >>= 1) {
        if (tid < off) sd[tid] += sd[tid + off];
        __syncthreads();
    }
    if (tid == 0)
        out[2 * NROWS] = (float)(sd[0] / ((double)NROWS * (double)T));
}

// ---------------------------------------------------------------------------
extern "C" void kernel_launch(void* const* d_in, const int* in_sizes, int n_in,
                              void* d_out, int out_size) {
    const float* W    = (const float*)d_in[0];
    const float* bias = (const float*)d_in[1];
    const int*   sent = (const int*)d_in[2];
    float* out = (float*)d_out;

    reset_k<<<1, 1>>>();
    dim3 tb(32, 8);
    dim3 tg(CDIM / 32, T / 128);
    transpose_k<<<tg, tb>>>(W);
    gather_k<<<NROWS / ROWSPB, 256>>>(bias, sent);
    combine_k<<<NROWS / 32, 256>>>(bias, sent, W, out);
    fixup_k<<<128, 256>>>(bias, sent, W, out);
    finalize_k<<<1, 256>>>(out);
}

// round 10
// speedup vs baseline: 13.7206x; 1.1516x over previous
#include <cuda_runtime.h>

#define V 4096
#define T 4096
#define FW 5
#define BATCH 64
#define SLEN 512
#define NROWS (BATCH * SLEN)   // 32768
#define CDIM (V * FW)          // 20480
#define WMAX 0.06f
#define INVQ (127.0f / WMAX)
#define QUANT (WMAX / 127.0f)
#define MARGIN 2.5e-3f
#define MAXC 16
#define TIE_EPS 4e-6f
#define ROWSPB 4

// int8 transposed weights W8[k][v][t] -- 84 MB working set
__device__ signed char g_W8[(size_t)FW * V * T];
__device__ float g_c0[NROWS];
__device__ float g_mp[NROWS];
__device__ int   g_cnt[NROWS];
__device__ int   g_cand[NROWS][MAXC];
__device__ float g_rowent[NROWS];
__device__ int   g_flaglist[NROWS];
__device__ int   g_nflag;
__device__ int   g_clamped;

// ---------------------------------------------------------------------------
__global__ void reset_k() { g_nflag = 0; g_clamped = 0; }

// ---------------------------------------------------------------------------
// Kernel 1: transpose W[t][v][k] f32 -> W8[k][v][t] int8, fixed global scale.
// ---------------------------------------------------------------------------
__global__ __launch_bounds__(256) void transpose_k(const float* __restrict__ W) {
    __shared__ float tile[128][33];     // [t][c]
    int c0 = blockIdx.x << 5;
    int t0 = blockIdx.y << 7;
    int tx = threadIdx.x;
    int ty = threadIdx.y;

#pragma unroll
    for (int j = 0; j < 16; j++) {
        int r = j * 8 + ty;
        tile[r][tx] = W[(size_t)(t0 + r) * CDIM + c0 + tx];
    }
    __syncthreads();

    bool clamp = false;
#pragma unroll
    for (int j = 0; j < 4; j++) {
        int c = j * 8 + ty;
        int cc = c0 + c;
        int v = cc / 5;
        int k = cc - 5 * v;
        int q[4];
#pragma unroll
        for (int i = 0; i < 4; i++) {
            float w = tile[4 * tx + i][c];
            int qi = __float2int_rn(w * INVQ);
            if (qi > 127) { qi = 127; clamp = true; }
            if (qi < -127) { qi = -127; clamp = true; }
            q[i] = qi;
        }
        unsigned int pk = (q[0] & 0xff) | ((q[1] & 0xff) << 8) |
                          ((q[2] & 0xff) << 16) | ((unsigned int)(q[3] & 0xff) << 24);
        *(unsigned int*)(g_W8 + ((size_t)k * V + v) * T + t0 + 4 * tx) = pk;
    }
    if (clamp) atomicExch(&g_clamped, 1);
}

// ---------------------------------------------------------------------------
__device__ __forceinline__ void acc_u16(unsigned int* a, uint4 w) {
    const unsigned int* wu = (const unsigned int*)&w;
#pragma unroll
    for (int q = 0; q < 4; q++) {
        unsigned int u = wu[q] ^ 0x80808080u;
        a[2 * q + 0] += __byte_perm(u, 0, 0x4140);
        a[2 * q + 1] += __byte_perm(u, 0, 0x4342);
    }
}

// ---------------------------------------------------------------------------
// Kernel 2: int8 gather, 4 rows/block, 16 t/thread. Tokens hoisted; interior
// blocks take a fully unconditional load path (front-batched LDG, high MLP).
// ---------------------------------------------------------------------------
__global__ __launch_bounds__(256, 3) void gather_k(const float* __restrict__ bias,
                                                   const int* __restrict__ sent) {
    int r0 = blockIdx.x * ROWSPB;
    int bb = r0 >> 9;
    int s0r = r0 & 511;
    int tid = threadIdx.x;
    int lane = tid & 31, warp = tid >> 5;
    int tb16 = tid * 16;

    __shared__ float red[8];
    __shared__ float red2[8];
    __shared__ float bc[2];
    __shared__ int scand[MAXC];
    __shared__ int scnt;

    unsigned int acc[ROWSPB][8];
#pragma unroll
    for (int rr = 0; rr < ROWSPB; rr++)
#pragma unroll
        for (int j = 0; j < 8; j++) acc[rr][j] = 0;
    int nvalid[ROWSPB];

    const signed char* wb = g_W8 + tb16;

    if (s0r >= 2 && s0r + ROWSPB - 1 + 2 <= SLEN - 1) {
        // ---- fast path: all 20 (k,rr) in range. Hoist 8 tokens, then
        // unconditional batched loads (4 independent per k step).
        int toks[8];
#pragma unroll
        for (int i = 0; i < 8; i++)
            toks[i] = __ldg(&sent[(bb << 9) + s0r - 2 + i]);
#pragma unroll
        for (int rr = 0; rr < ROWSPB; rr++) nvalid[rr] = FW;

#pragma unroll
        for (int k = 0; k < FW; k++) {
            uint4 w[ROWSPB];
#pragma unroll
            for (int rr = 0; rr < ROWSPB; rr++)
                w[rr] = *(const uint4*)(wb + ((size_t)k * V + toks[k + rr]) * T);
#pragma unroll
            for (int rr = 0; rr < ROWSPB; rr++)
                acc_u16(acc[rr], w[rr]);
        }
    } else {
        // ---- edge path (2 blocks per 128): predicated
#pragma unroll
        for (int rr = 0; rr < ROWSPB; rr++) nvalid[rr] = 0;
#pragma unroll
        for (int k = 0; k < FW; k++) {
#pragma unroll
            for (int rr = 0; rr < ROWSPB; rr++) {
                int p = s0r + rr + k - 2;
                if (p >= 0 && p < SLEN) {
                    nvalid[rr]++;
                    int tok = __ldg(&sent[(bb << 9) + p]);
                    uint4 w = *(const uint4*)(wb + ((size_t)k * V + tok) * T);
                    acc_u16(acc[rr], w);
                }
            }
        }
    }

    // bias loaded at epilogue (keeps load-phase registers lean)
    float bs[16];
    {
        const float4* b4 = (const float4*)(bias + tb16);
#pragma unroll
        for (int i = 0; i < 4; i++) {
            float4 t4 = b4[i];
            bs[4 * i + 0] = t4.x; bs[4 * i + 1] = t4.y;
            bs[4 * i + 2] = t4.z; bs[4 * i + 3] = t4.w;
        }
    }

    for (int rr = 0; rr < ROWSPB; rr++) {
        int row = r0 + rr;
        int off = 128 * nvalid[rr];

        float lv[16];
#pragma unroll
        for (int q = 0; q < 8; q++) {
            int lo = (int)(acc[rr][q] & 0xffffu) - off;
            int hi = (int)(acc[rr][q] >> 16) - off;
            lv[2 * q + 0] = fmaf((float)lo, QUANT, bs[2 * q + 0]);
            lv[2 * q + 1] = fmaf((float)hi, QUANT, bs[2 * q + 1]);
        }

        float vmax = lv[0];
#pragma unroll
        for (int j = 1; j < 16; j++) vmax = fmaxf(vmax, lv[j]);
#pragma unroll
        for (int o = 16; o > 0; o >>= 1)
            vmax = fmaxf(vmax, __shfl_xor_sync(0xffffffffu, vmax, o));
        if (lane == 0) red[warp] = vmax;
        if (tid == 0) scnt = 0;
        __syncthreads();
        if (warp == 0) {
            float v = (lane < 8) ? red[lane] : -1e30f;
#pragma unroll
            for (int o = 4; o > 0; o >>= 1)
                v = fmaxf(v, __shfl_xor_sync(0xffffffffu, v, o));
            if (lane == 0) bc[0] = v;
        }
        __syncthreads();
        float mc = bc[0];

        float s0 = 0.f, s1 = 0.f;
        float thr = mc - MARGIN;
#pragma unroll
        for (int j = 0; j < 16; j++) {
            float d = lv[j] - mc;
            float e = __expf(d);
            s0 += e;
            s1 += d * e;
            if (lv[j] >= thr) {
                int idx = atomicAdd(&scnt, 1);
                if (idx < MAXC) scand[idx] = tb16 + j;
            }
        }
#pragma unroll
        for (int o = 16; o > 0; o >>= 1) {
            s0 += __shfl_xor_sync(0xffffffffu, s0, o);
            s1 += __shfl_xor_sync(0xffffffffu, s1, o);
        }
        if (lane == 0) { red[warp] = s0; red2[warp] = s1; }
        __syncthreads();
        if (warp == 0) {
            float a = (lane < 8) ? red[lane] : 0.f;
            float b = (lane < 8) ? red2[lane] : 0.f;
#pragma unroll
            for (int o = 4; o > 0; o >>= 1) {
                a += __shfl_xor_sync(0xffffffffu, a, o);
                b += __shfl_xor_sync(0xffffffffu, b, o);
            }
            if (lane == 0) { bc[0] = a; bc[1] = b; }
        }
        __syncthreads();

        int rawn = scnt;
        int nc = rawn < MAXC ? rawn : MAXC;
        if (tid < MAXC) g_cand[row][tid] = (tid < nc) ? scand[tid] : 0;
        if (tid == 0) {
            float S0 = bc[0], S1 = bc[1];
            float c0 = logf(S0);
            g_c0[row] = c0;
            g_mp[row] = mc;
            g_cnt[row] = rawn;
            g_rowent[row] = c0 - S1 / S0;
        }
        __syncthreads();
    }
}

// ---------------------------------------------------------------------------
__device__ __forceinline__ float exact_logit(const float* __restrict__ bias,
                                             const float* __restrict__ W,
                                             const int* toks, int t) {
    float l = __ldg(&bias[t]);
#pragma unroll
    for (int k = 0; k < FW; k++)
        if (toks[k] >= 0)
            l += __ldg(&W[(size_t)t * CDIM + toks[k] * 5 + k]);
    return l;
}

// ---------------------------------------------------------------------------
// Kernel 3: combine. 8 lanes/row; exact fp32 recheck of candidates.
// ---------------------------------------------------------------------------
__global__ __launch_bounds__(256) void combine_k(const float* __restrict__ bias,
                                                 const int* __restrict__ sent,
                                                 const float* __restrict__ W,
                                                 float* __restrict__ out) {
    int tid = threadIdx.x;
    int row = blockIdx.x * 32 + (tid >> 3);
    int lane8 = tid & 7;
    int bb = row >> 9, s = row & 511;

    int rawn = g_cnt[row];
    int nc = rawn < MAXC ? rawn : MAXC;
    float mp = g_mp[row], c0 = g_c0[row];
    int clamped = g_clamped;

    int toks[FW];
#pragma unroll
    for (int k = 0; k < FW; k++) {
        int p = s + k - 2;
        toks[k] = (p >= 0 && p < SLEN) ? __ldg(&sent[(bb << 9) + p]) : -1;
    }

    float le[2]; int te[2];
#pragma unroll
    for (int i = 0; i < 2; i++) {
        int ci = lane8 + 8 * i;
        if (ci < nc) { te[i] = g_cand[row][ci]; le[i] = exact_logit(bias, W, toks, te[i]); }
        else         { te[i] = 0x7fffffff;      le[i] = -1e30f; }
    }

    float m = fmaxf(le[0], le[1]);
#pragma unroll
    for (int o = 4; o > 0; o >>= 1)
        m = fmaxf(m, __shfl_xor_sync(0xffffffffu, m, o, 8));
    float cc = c0 + (mp - m);

    float blp = -1e30f; int bt = 0x7fffffff;
    int near = 0;
#pragma unroll
    for (int i = 0; i < 2; i++) {
        if (te[i] != 0x7fffffff) {
            float lp = (le[i] - m) - cc;
            if (lp > blp || (lp == blp && te[i] < bt)) { blp = lp; bt = te[i]; }
            if (le[i] > m - TIE_EPS) near++;
        }
    }
#pragma unroll
    for (int o = 4; o > 0; o >>= 1) {
        float olp = __shfl_xor_sync(0xffffffffu, blp, o, 8);
        int   ot  = __shfl_xor_sync(0xffffffffu, bt,  o, 8);
        int   on  = __shfl_xor_sync(0xffffffffu, near, o, 8);
        if (olp > blp || (olp == blp && ot < bt)) { blp = olp; bt = ot; }
        near += on;
    }

    if (lane8 == 0) {
        out[row] = (float)bt;
        out[NROWS + row] = blp;
        if (near >= 2 || rawn > MAXC || clamped) {
            int ix = atomicAdd(&g_nflag, 1);
            g_flaglist[ix] = row;
        }
    }
}

// ---------------------------------------------------------------------------
// Kernel 4: exact fixup for flagged rows (full 4096 fp32 logits).
// ---------------------------------------------------------------------------
__global__ __launch_bounds__(256) void fixup_k(const float* __restrict__ bias,
                                               const int* __restrict__ sent,
                                               const float* __restrict__ W,
                                               float* __restrict__ out) {
    __shared__ float sv[256];
    __shared__ int   si[256];
    __shared__ float sb[1];
    int tid = threadIdx.x;
    int nf = g_nflag;

    for (int it = blockIdx.x; it < nf; it += gridDim.x) {
        int row = g_flaglist[it];
        int bb = row >> 9, s = row & 511;
        int toks[FW];
#pragma unroll
        for (int k = 0; k < FW; k++) {
            int p = s + k - 2;
            toks[k] = (p >= 0 && p < SLEN) ? __ldg(&sent[(bb << 9) + p]) : -1;
        }
        float lv[16];
        float vmax = -1e30f;
#pragma unroll
        for (int j = 0; j < 16; j++) {
            lv[j] = exact_logit(bias, W, toks, tid * 16 + j);
            vmax = fmaxf(vmax, lv[j]);
        }
        sv[tid] = vmax;
        __syncthreads();
#pragma unroll
        for (int off = 128; off > 0; off >>= 1) {
            if (tid < off) sv[tid] = fmaxf(sv[tid], sv[tid + off]);
            __syncthreads();
        }
        float m = sv[0];
        __syncthreads();

        float s0 = 0.f;
#pragma unroll
        for (int j = 0; j < 16; j++) s0 += expf(lv[j] - m);
        sv[tid] = s0;
        __syncthreads();
#pragma unroll
        for (int off = 128; off > 0; off >>= 1) {
            if (tid < off) sv[tid] += sv[tid + off];
            __syncthreads();
        }
        if (tid == 0) sb[0] = logf(sv[0]);
        __syncthreads();
        float c = sb[0];
        __syncthreads();

        float blp = -1e30f;
        int bt = 0;
#pragma unroll
        for (int j = 0; j < 16; j++) {
            float lp = (lv[j] - m) - c;
            if (lp > blp) { blp = lp; bt = tid * 16 + j; }
        }
        sv[tid] = blp; si[tid] = bt;
        __syncthreads();
#pragma unroll
        for (int off = 128; off > 0; off >>= 1) {
            if (tid < off) {
                float ov = sv[tid + off];
                int   oi = si[tid + off];
                if (ov > sv[tid] || (ov == sv[tid] && oi < si[tid])) {
                    sv[tid] = ov; si[tid] = oi;
                }
            }
            __syncthreads();
        }
        if (tid == 0) {
            out[row] = (float)si[0];
            out[NROWS + row] = sv[0];
        }
        __syncthreads();
    }
}

// ---------------------------------------------------------------------------
__global__ __launch_bounds__(256) void finalize_k(float* __restrict__ out) {
    __shared__ double sd[256];
    int tid = threadIdx.x;
    double a = 0.0;
    for (int i = tid; i < NROWS; i += 256) a += (double)g_rowent[i];
    sd[tid] = a;
    __syncthreads();
#pragma unroll
    for (int off = 128; off > 0; off >>= 1) {
        if (tid < off) sd[tid] += sd[tid + off];
        __syncthreads();
    }
    if (tid == 0)
        out[2 * NROWS] = (float)(sd[0] / ((double)NROWS * (double)T));
}

// ---------------------------------------------------------------------------
extern "C" void kernel_launch(void* const* d_in, const int* in_sizes, int n_in,
                              void* d_out, int out_size) {
    const float* W    = (const float*)d_in[0];
    const float* bias = (const float*)d_in[1];
    const int*   sent = (const int*)d_in[2];
    float* out = (float*)d_out;

    reset_k<<<1, 1>>>();
    dim3 tb(32, 8);
    dim3 tg(CDIM / 32, T / 128);
    transpose_k<<<tg, tb>>>(W);
    gather_k<<<NROWS / ROWSPB, 256>>>(bias, sent);
    combine_k<<<NROWS / 32, 256>>>(bias, sent, W, out);
    fixup_k<<<128, 256>>>(bias, sent, W, out);
    finalize_k<<<1, 256>>>(out);
}

// round 11
// speedup vs baseline: 15.9734x; 1.1642x over previous
#include <cuda_runtime.h>

#define V 4096
#define T 4096
#define FW 5
#define BATCH 64
#define SLEN 512
#define NROWS (BATCH * SLEN)   // 32768
#define CDIM (V * FW)          // 20480
#define WMAX 0.06f
#define INVQ (127.0f / WMAX)
#define QUANT (WMAX / 127.0f)
#define MARGIN_INT 10
#define MAXC 16
#define TIE_EPS 4e-6f
#define ROWSPB 4

// u8 excess-128 transposed weights W8[k][v][t] -- 84 MB working set
__device__ unsigned char g_W8[(size_t)FW * V * T];
// bias quantized to the same grid, excess-1024, packed u16x2
__device__ unsigned int g_biasq[T / 2];
__device__ float g_c0[NROWS];
__device__ float g_mp[NROWS];
__device__ int   g_cnt[NROWS];
__device__ int   g_cand[NROWS][MAXC];
__device__ float g_rowent[NROWS];
__device__ int   g_flaglist[NROWS];
__device__ int   g_nflag;
__device__ int   g_clamped;

// ---------------------------------------------------------------------------
__global__ void reset_k() { g_nflag = 0; g_clamped = 0; }

// ---------------------------------------------------------------------------
// bias -> integer grid (excess 1024), packed pairs. 1 block, 256 threads.
// ---------------------------------------------------------------------------
__global__ __launch_bounds__(256) void biasq_k(const float* __restrict__ bias) {
    int tid = threadIdx.x;
#pragma unroll
    for (int j = 0; j < 8; j++) {
        int t = tid * 16 + 2 * j;
        int b0 = __float2int_rn(__ldg(&bias[t]) * INVQ) + 1024;
        int b1 = __float2int_rn(__ldg(&bias[t + 1]) * INVQ) + 1024;
        b0 = min(max(b0, 0), 4095);
        b1 = min(max(b1, 0), 4095);
        g_biasq[tid * 8 + j] = (unsigned int)b0 | ((unsigned int)b1 << 16);
    }
}

// ---------------------------------------------------------------------------
// Kernel: transpose W[t][v][k] f32 -> W8[k][v][t] u8 excess-128, fixed scale.
// ---------------------------------------------------------------------------
__global__ __launch_bounds__(256) void transpose_k(const float* __restrict__ W) {
    __shared__ float tile[128][33];     // [t][c]
    int c0 = blockIdx.x << 5;
    int t0 = blockIdx.y << 7;
    int tx = threadIdx.x;
    int ty = threadIdx.y;

#pragma unroll
    for (int j = 0; j < 16; j++) {
        int r = j * 8 + ty;
        tile[r][tx] = W[(size_t)(t0 + r) * CDIM + c0 + tx];
    }
    __syncthreads();

    bool clamp = false;
#pragma unroll
    for (int j = 0; j < 4; j++) {
        int c = j * 8 + ty;
        int cc = c0 + c;
        int v = cc / 5;
        int k = cc - 5 * v;
        unsigned int q[4];
#pragma unroll
        for (int i = 0; i < 4; i++) {
            float w = tile[4 * tx + i][c];
            int qi = __float2int_rn(w * INVQ);
            if (qi > 127) { qi = 127; clamp = true; }
            if (qi < -127) { qi = -127; clamp = true; }
            q[i] = (unsigned int)(qi + 128);   // excess-128
        }
        unsigned int pk = q[0] | (q[1] << 8) | (q[2] << 16) | (q[3] << 24);
        *(unsigned int*)(g_W8 + ((size_t)k * V + v) * T + t0 + 4 * tx) = pk;
    }
    if (clamp) atomicExch(&g_clamped, 1);
}

// ---------------------------------------------------------------------------
__device__ __forceinline__ void acc_u16(unsigned int* a, uint4 w) {
    const unsigned int* wu = (const unsigned int*)&w;
#pragma unroll
    for (int q = 0; q < 4; q++) {
        a[2 * q + 0] += __byte_perm(wu[q], 0, 0x4140);
        a[2 * q + 1] += __byte_perm(wu[q], 0, 0x4342);
    }
}

// ---------------------------------------------------------------------------
// Gather: 4 rows/block, 16 t/thread, integer logits, shift-free softmax,
// single stats pass + 3 barrier phases for all 4 rows.
// ---------------------------------------------------------------------------
__global__ __launch_bounds__(256, 3) void gather_k(const int* __restrict__ sent) {
    int r0 = blockIdx.x * ROWSPB;
    int bb = r0 >> 9;
    int s0r = r0 & 511;
    int tid = threadIdx.x;
    int lane = tid & 31, warp = tid >> 5;
    int tb16 = tid * 16;

    __shared__ float sm0[ROWSPB][8];
    __shared__ float sm1[ROWSPB][8];
    __shared__ int   smm[ROWSPB][8];
    __shared__ int   sfin[ROWSPB];       // final integer max per row
    __shared__ int   scand[ROWSPB][MAXC];
    __shared__ int   scnt[ROWSPB];

    unsigned int acc[ROWSPB][8];
#pragma unroll
    for (int rr = 0; rr < ROWSPB; rr++)
#pragma unroll
        for (int j = 0; j < 8; j++) acc[rr][j] = 0;
    int nvalid[ROWSPB];

    const unsigned char* wb = g_W8 + tb16;

    if (s0r >= 2 && s0r + ROWSPB + 1 <= SLEN) {
        // fast path: all 20 (k,rr) in range
        int toks[8];
#pragma unroll
        for (int i = 0; i < 8; i++)
            toks[i] = __ldg(&sent[(bb << 9) + s0r - 2 + i]);
#pragma unroll
        for (int rr = 0; rr < ROWSPB; rr++) nvalid[rr] = FW;

#pragma unroll
        for (int k = 0; k < FW; k++) {
            uint4 w[ROWSPB];
#pragma unroll
            for (int rr = 0; rr < ROWSPB; rr++)
                w[rr] = *(const uint4*)(wb + ((size_t)k * V + toks[k + rr]) * T);
#pragma unroll
            for (int rr = 0; rr < ROWSPB; rr++)
                acc_u16(acc[rr], w[rr]);
        }
    } else {
#pragma unroll
        for (int rr = 0; rr < ROWSPB; rr++) nvalid[rr] = 0;
#pragma unroll
        for (int k = 0; k < FW; k++) {
#pragma unroll
            for (int rr = 0; rr < ROWSPB; rr++) {
                int p = s0r + rr + k - 2;
                if (p >= 0 && p < SLEN) {
                    nvalid[rr]++;
                    int tok = __ldg(&sent[(bb << 9) + p]);
                    uint4 w = *(const uint4*)(wb + ((size_t)k * V + tok) * T);
                    acc_u16(acc[rr], w);
                }
            }
        }
    }

    // bias (integer grid) for this thread's 16 t
    unsigned int biasq[8];
    {
        const uint4* b4 = (const uint4*)(g_biasq + tid * 8);
        uint4 a = b4[0], b = b4[1];
        biasq[0] = a.x; biasq[1] = a.y; biasq[2] = a.z; biasq[3] = a.w;
        biasq[4] = b.x; biasq[5] = b.y; biasq[6] = b.z; biasq[7] = b.w;
    }

    // ---- phase A: per-thread stats for all rows (no barriers)
    int   mxi[ROWSPB];
    float s0[ROWSPB], s1[ROWSPB];
#pragma unroll
    for (int rr = 0; rr < ROWSPB; rr++) {
        int base = 128 * nvalid[rr] + 1024;
        float fb = -QUANT * (float)base;
        int mx = 0;
        float a0 = 0.f, a1 = 0.f;
#pragma unroll
        for (int j = 0; j < 8; j++) {
            unsigned int lvp = __vadd2(acc[rr][j], biasq[j]);
            int lo = (int)(lvp & 0xffffu);
            int hi = (int)(lvp >> 16);
            mx = max(mx, max(lo, hi));
            float x0 = fmaf((float)lo, QUANT, fb);
            float x1 = fmaf((float)hi, QUANT, fb);
            float e0 = __expf(x0);
            float e1 = __expf(x1);
            a0 += e0 + e1;
            a1 = fmaf(x0, e0, a1);
            a1 = fmaf(x1, e1, a1);
        }
        mxi[rr] = mx; s0[rr] = a0; s1[rr] = a1;
    }

    // warp-level reduce
#pragma unroll
    for (int rr = 0; rr < ROWSPB; rr++) {
#pragma unroll
        for (int o = 16; o > 0; o >>= 1) {
            mxi[rr] = max(mxi[rr], __shfl_xor_sync(0xffffffffu, mxi[rr], o));
            s0[rr] += __shfl_xor_sync(0xffffffffu, s0[rr], o);
            s1[rr] += __shfl_xor_sync(0xffffffffu, s1[rr], o);
        }
        if (lane == 0) { sm0[rr][warp] = s0[rr]; sm1[rr][warp] = s1[rr]; smm[rr][warp] = mxi[rr]; }
    }
    if (tid < ROWSPB) scnt[tid] = 0;
    __syncthreads();

    // ---- phase B: warps 0..3 finalize one row each (lanes 0..7)
    if (warp < ROWSPB && lane < 8) {
        int rr = warp;
        float a0 = sm0[rr][lane];
        float a1 = sm1[rr][lane];
        int   mx = smm[rr][lane];
#pragma unroll
        for (int o = 4; o > 0; o >>= 1) {
            a0 += __shfl_xor_sync(0xffu, a0, o, 8);
            a1 += __shfl_xor_sync(0xffu, a1, o, 8);
            mx = max(mx, __shfl_xor_sync(0xffu, mx, o, 8));
        }
        if (lane == 0) {
            int row = r0 + rr;
            float c0 = logf(a0);
            g_c0[row] = c0;
            g_mp[row] = 0.f;                 // shift-free reference
            g_rowent[row] = c0 - a1 / a0;
            sfin[rr] = mx;
        }
    }
    __syncthreads();

    // ---- phase C: integer candidate scan
#pragma unroll
    for (int rr = 0; rr < ROWSPB; rr++) {
        int thr = sfin[rr] - MARGIN_INT;
#pragma unroll
        for (int j = 0; j < 8; j++) {
            unsigned int lvp = __vadd2(acc[rr][j], biasq[j]);
            int lo = (int)(lvp & 0xffffu);
            int hi = (int)(lvp >> 16);
            if (lo >= thr) {
                int ix = atomicAdd(&scnt[rr], 1);
                if (ix < MAXC) scand[rr][ix] = tb16 + 2 * j;
            }
            if (hi >= thr) {
                int ix = atomicAdd(&scnt[rr], 1);
                if (ix < MAXC) scand[rr][ix] = tb16 + 2 * j + 1;
            }
        }
    }
    __syncthreads();

    if (tid < ROWSPB) g_cnt[r0 + tid] = scnt[tid];
    if (tid < ROWSPB * MAXC) {
        int rr = tid >> 4, sl = tid & 15;
        int n = scnt[rr] < MAXC ? scnt[rr] : MAXC;
        g_cand[r0 + rr][sl] = (sl < n) ? scand[rr][sl] : 0;
    }
}

// ---------------------------------------------------------------------------
__device__ __forceinline__ float exact_logit(const float* __restrict__ bias,
                                             const float* __restrict__ W,
                                             const int* toks, int t) {
    float l = __ldg(&bias[t]);
#pragma unroll
    for (int k = 0; k < FW; k++)
        if (toks[k] >= 0)
            l += __ldg(&W[(size_t)t * CDIM + toks[k] * 5 + k]);
    return l;
}

// ---------------------------------------------------------------------------
// Combine: 8 lanes/row; exact fp32 recheck of candidates; flag overflow,
// near-ties, or quant clamp.
// ---------------------------------------------------------------------------
__global__ __launch_bounds__(256) void combine_k(const float* __restrict__ bias,
                                                 const int* __restrict__ sent,
                                                 const float* __restrict__ W,
                                                 float* __restrict__ out) {
    int tid = threadIdx.x;
    int row = blockIdx.x * 32 + (tid >> 3);
    int lane8 = tid & 7;
    int bb = row >> 9, s = row & 511;

    int rawn = g_cnt[row];
    int nc = rawn < MAXC ? rawn : MAXC;
    float mp = g_mp[row], c0 = g_c0[row];
    int clamped = g_clamped;

    int toks[FW];
#pragma unroll
    for (int k = 0; k < FW; k++) {
        int p = s + k - 2;
        toks[k] = (p >= 0 && p < SLEN) ? __ldg(&sent[(bb << 9) + p]) : -1;
    }

    float le[2]; int te[2];
#pragma unroll
    for (int i = 0; i < 2; i++) {
        int ci = lane8 + 8 * i;
        if (ci < nc) { te[i] = g_cand[row][ci]; le[i] = exact_logit(bias, W, toks, te[i]); }
        else         { te[i] = 0x7fffffff;      le[i] = -1e30f; }
    }

    float m = fmaxf(le[0], le[1]);
#pragma unroll
    for (int o = 4; o > 0; o >>= 1)
        m = fmaxf(m, __shfl_xor_sync(0xffffffffu, m, o, 8));
    float cc = c0 + (mp - m);

    float blp = -1e30f; int bt = 0x7fffffff;
    int near = 0;
#pragma unroll
    for (int i = 0; i < 2; i++) {
        if (te[i] != 0x7fffffff) {
            float lp = (le[i] - m) - cc;
            if (lp > blp || (lp == blp && te[i] < bt)) { blp = lp; bt = te[i]; }
            if (le[i] > m - TIE_EPS) near++;
        }
    }
#pragma unroll
    for (int o = 4; o > 0; o >>= 1) {
        float olp = __shfl_xor_sync(0xffffffffu, blp, o, 8);
        int   ot  = __shfl_xor_sync(0xffffffffu, bt,  o, 8);
        int   on  = __shfl_xor_sync(0xffffffffu, near, o, 8);
        if (olp > blp || (olp == blp && ot < bt)) { blp = olp; bt = ot; }
        near += on;
    }

    if (lane8 == 0) {
        out[row] = (float)bt;
        out[NROWS + row] = blp;
        if (near >= 2 || rawn > MAXC || clamped) {
            int ix = atomicAdd(&g_nflag, 1);
            g_flaglist[ix] = row;
        }
    }
}

// ---------------------------------------------------------------------------
// Exact fixup for flagged rows (full 4096 fp32 logits).
// ---------------------------------------------------------------------------
__global__ __launch_bounds__(256) void fixup_k(const float* __restrict__ bias,
                                               const int* __restrict__ sent,
                                               const float* __restrict__ W,
                                               float* __restrict__ out) {
    __shared__ float sv[256];
    __shared__ int   si[256];
    __shared__ float sb[1];
    int tid = threadIdx.x;
    int nf = g_nflag;

    for (int it = blockIdx.x; it < nf; it += gridDim.x) {
        int row = g_flaglist[it];
        int bb = row >> 9, s = row & 511;
        int toks[FW];
#pragma unroll
        for (int k = 0; k < FW; k++) {
            int p = s + k - 2;
            toks[k] = (p >= 0 && p < SLEN) ? __ldg(&sent[(bb << 9) + p]) : -1;
        }
        float lv[16];
        float vmax = -1e30f;
#pragma unroll
        for (int j = 0; j < 16; j++) {
            lv[j] = exact_logit(bias, W, toks, tid * 16 + j);
            vmax = fmaxf(vmax, lv[j]);
        }
        sv[tid] = vmax;
        __syncthreads();
#pragma unroll
        for (int off = 128; off > 0; off >>= 1) {
            if (tid < off) sv[tid] = fmaxf(sv[tid], sv[tid + off]);
            __syncthreads();
        }
        float m = sv[0];
        __syncthreads();

        float s0 = 0.f;
#pragma unroll
        for (int j = 0; j < 16; j++) s0 += expf(lv[j] - m);
        sv[tid] = s0;
        __syncthreads();
#pragma unroll
        for (int off = 128; off > 0; off >>= 1) {
            if (tid < off) sv[tid] += sv[tid + off];
            __syncthreads();
        }
        if (tid == 0) sb[0] = logf(sv[0]);
        __syncthreads();
        float c = sb[0];
        __syncthreads();

        float blp = -1e30f;
        int bt = 0;
#pragma unroll
        for (int j = 0; j < 16; j++) {
            float lp = (lv[j] - m) - c;
            if (lp > blp) { blp = lp; bt = tid * 16 + j; }
        }
        sv[tid] = blp; si[tid] = bt;
        __syncthreads();
#pragma unroll
        for (int off = 128; off > 0; off >>= 1) {
            if (tid < off) {
                float ov = sv[tid + off];
                int   oi = si[tid + off];
                if (ov > sv[tid] || (ov == sv[tid] && oi < si[tid])) {
                    sv[tid] = ov; si[tid] = oi;
                }
            }
            __syncthreads();
        }
        if (tid == 0) {
            out[row] = (float)si[0];
            out[NROWS + row] = sv[0];
        }
        __syncthreads();
    }
}

// ---------------------------------------------------------------------------
__global__ __launch_bounds__(256) void finalize_k(float* __restrict__ out) {
    __shared__ double sd[256];
    int tid = threadIdx.x;
    double a = 0.0;
    for (int i = tid; i < NROWS; i += 256) a += (double)g_rowent[i];
    sd[tid] = a;
    __syncthreads();
#pragma unroll
    for (int off = 128; off > 0; off >>= 1) {
        if (tid < off) sd[tid] += sd[tid + off];
        __syncthreads();
    }
    if (tid == 0)
        out[2 * NROWS] = (float)(sd[0] / ((double)NROWS * (double)T));
}

// ---------------------------------------------------------------------------
extern "C" void kernel_launch(void* const* d_in, const int* in_sizes, int n_in,
                              void* d_out, int out_size) {
    const float* W    = (const float*)d_in[0];
    const float* bias = (const float*)d_in[1];
    const int*   sent = (const int*)d_in[2];
    float* out = (float*)d_out;

    reset_k<<<1, 1>>>();                               // launch 1
    biasq_k<<<1, 256>>>(bias);                         // launch 2
    dim3 tb(32, 8);
    dim3 tg(CDIM / 32, T / 128);
    transpose_k<<<tg, tb>>>(W);                        // launch 3
    gather_k<<<NROWS / ROWSPB, 256>>>(sent);           // launch 4 (ncu capture slot)
    combine_k<<<NROWS / 32, 256>>>(bias, sent, W, out);
    fixup_k<<<128, 256>>>(bias, sent, W, out);
    finalize_k<<<1, 256>>>(out);
}

// round 12
// speedup vs baseline: 17.5932x; 1.1014x over previous
#include <cuda_runtime.h>

#define V 4096
#define T 4096
#define FW 5
#define BATCH 64
#define SLEN 512
#define NROWS (BATCH * SLEN)   // 32768
#define CDIM (V * FW)          // 20480
#define WMAX 0.06f
#define INVQ (127.0f / WMAX)
#define QUANT (WMAX / 127.0f)
#define MARGIN_INT 10
#define MAXC 16
#define TIE_EPS 4e-6f
#define ROWSPB 2

// u8 excess-128 transposed weights W8[k][v][t] -- 84 MB working set
__device__ unsigned char g_W8[(size_t)FW * V * T];
// bias quantized to the same grid, excess-1024, packed u16x2
__device__ unsigned int g_biasq[T / 2];
__device__ float g_c0[NROWS];
__device__ float g_mp[NROWS];
__device__ int   g_cnt[NROWS];
__device__ int   g_cand[NROWS][MAXC];
__device__ float g_rowent[NROWS];
__device__ int   g_flaglist[NROWS];
__device__ int   g_nflag;
__device__ int   g_clamped;

// ---------------------------------------------------------------------------
__global__ void reset_k() { g_nflag = 0; g_clamped = 0; }

// ---------------------------------------------------------------------------
__global__ __launch_bounds__(256) void biasq_k(const float* __restrict__ bias) {
    int tid = threadIdx.x;
#pragma unroll
    for (int j = 0; j < 8; j++) {
        int t = tid * 16 + 2 * j;
        int b0 = __float2int_rn(__ldg(&bias[t]) * INVQ) + 1024;
        int b1 = __float2int_rn(__ldg(&bias[t + 1]) * INVQ) + 1024;
        b0 = min(max(b0, 0), 4095);
        b1 = min(max(b1, 0), 4095);
        g_biasq[tid * 8 + j] = (unsigned int)b0 | ((unsigned int)b1 << 16);
    }
}

// ---------------------------------------------------------------------------
// transpose W[t][v][k] f32 -> W8[k][v][t] u8 excess-128, fixed scale.
// ---------------------------------------------------------------------------
__global__ __launch_bounds__(256) void transpose_k(const float* __restrict__ W) {
    __shared__ float tile[128][33];     // [t][c]
    int c0 = blockIdx.x << 5;
    int t0 = blockIdx.y << 7;
    int tx = threadIdx.x;
    int ty = threadIdx.y;

#pragma unroll
    for (int j = 0; j < 16; j++) {
        int r = j * 8 + ty;
        tile[r][tx] = W[(size_t)(t0 + r) * CDIM + c0 + tx];
    }
    __syncthreads();

    bool clamp = false;
#pragma unroll
    for (int j = 0; j < 4; j++) {
        int c = j * 8 + ty;
        int cc = c0 + c;
        int v = cc / 5;
        int k = cc - 5 * v;
        unsigned int q[4];
#pragma unroll
        for (int i = 0; i < 4; i++) {
            float w = tile[4 * tx + i][c];
            int qi = __float2int_rn(w * INVQ);
            if (qi > 127) { qi = 127; clamp = true; }
            if (qi < -127) { qi = -127; clamp = true; }
            q[i] = (unsigned int)(qi + 128);   // excess-128
        }
        unsigned int pk = q[0] | (q[1] << 8) | (q[2] << 16) | (q[3] << 24);
        *(unsigned int*)(g_W8 + ((size_t)k * V + v) * T + t0 + 4 * tx) = pk;
    }
    if (clamp) atomicExch(&g_clamped, 1);
}

// ---------------------------------------------------------------------------
__device__ __forceinline__ void acc_u16(unsigned int* a, uint4 w) {
    const unsigned int* wu = (const unsigned int*)&w;
#pragma unroll
    for (int q = 0; q < 4; q++) {
        a[2 * q + 0] += __byte_perm(wu[q], 0, 0x4140);
        a[2 * q + 1] += __byte_perm(wu[q], 0, 0x4342);
    }
}

// ---------------------------------------------------------------------------
// Gather: 2 rows/block (low regs -> 4 blocks/SM), 16 t/thread, integer
// logits, shift-free softmax, 3 barrier phases total.
// ---------------------------------------------------------------------------
__global__ __launch_bounds__(256, 4) void gather_k(const int* __restrict__ sent) {
    int r0 = blockIdx.x * ROWSPB;
    int bb = r0 >> 9;
    int s0r = r0 & 511;
    int tid = threadIdx.x;
    int lane = tid & 31, warp = tid >> 5;
    int tb16 = tid * 16;

    __shared__ float sm0[ROWSPB][8];
    __shared__ float sm1[ROWSPB][8];
    __shared__ int   smm[ROWSPB][8];
    __shared__ int   sfin[ROWSPB];
    __shared__ int   scand[ROWSPB][MAXC];
    __shared__ int   scnt[ROWSPB];

    unsigned int acc[ROWSPB][8];
#pragma unroll
    for (int rr = 0; rr < ROWSPB; rr++)
#pragma unroll
        for (int j = 0; j < 8; j++) acc[rr][j] = 0;
    int nvalid[ROWSPB];

    const unsigned char* wb = g_W8 + tb16;

    if (s0r >= 2 && s0r + ROWSPB + 1 <= SLEN) {
        // fast path: all (k,rr) in range; hoist 6 tokens; batched loads
        int toks[ROWSPB + 4];
#pragma unroll
        for (int i = 0; i < ROWSPB + 4; i++)
            toks[i] = __ldg(&sent[(bb << 9) + s0r - 2 + i]);
#pragma unroll
        for (int rr = 0; rr < ROWSPB; rr++) nvalid[rr] = FW;

#pragma unroll
        for (int k = 0; k < FW; k++) {
            uint4 w[ROWSPB];
#pragma unroll
            for (int rr = 0; rr < ROWSPB; rr++)
                w[rr] = *(const uint4*)(wb + ((size_t)k * V + toks[k + rr]) * T);
#pragma unroll
            for (int rr = 0; rr < ROWSPB; rr++)
                acc_u16(acc[rr], w[rr]);
        }
    } else {
#pragma unroll
        for (int rr = 0; rr < ROWSPB; rr++) nvalid[rr] = 0;
#pragma unroll
        for (int k = 0; k < FW; k++) {
#pragma unroll
            for (int rr = 0; rr < ROWSPB; rr++) {
                int p = s0r + rr + k - 2;
                if (p >= 0 && p < SLEN) {
                    nvalid[rr]++;
                    int tok = __ldg(&sent[(bb << 9) + p]);
                    uint4 w = *(const uint4*)(wb + ((size_t)k * V + tok) * T);
                    acc_u16(acc[rr], w);
                }
            }
        }
    }

    // bias (integer grid) for this thread's 16 t -- loaded at epilogue
    unsigned int biasq[8];
    {
        const uint4* b4 = (const uint4*)(g_biasq + tid * 8);
        uint4 a = b4[0], b = b4[1];
        biasq[0] = a.x; biasq[1] = a.y; biasq[2] = a.z; biasq[3] = a.w;
        biasq[4] = b.x; biasq[5] = b.y; biasq[6] = b.z; biasq[7] = b.w;
    }

    // ---- phase A: per-thread stats (no barriers)
    int   mxi[ROWSPB];
    float s0[ROWSPB], s1[ROWSPB];
#pragma unroll
    for (int rr = 0; rr < ROWSPB; rr++) {
        int base = 128 * nvalid[rr] + 1024;
        float fb = -QUANT * (float)base;
        int mx = 0;
        float a0 = 0.f, a1 = 0.f;
#pragma unroll
        for (int j = 0; j < 8; j++) {
            unsigned int lvp = __vadd2(acc[rr][j], biasq[j]);
            int lo = (int)(lvp & 0xffffu);
            int hi = (int)(lvp >> 16);
            mx = max(mx, max(lo, hi));
            float x0 = fmaf((float)lo, QUANT, fb);
            float x1 = fmaf((float)hi, QUANT, fb);
            float e0 = __expf(x0);
            float e1 = __expf(x1);
            a0 += e0 + e1;
            a1 = fmaf(x0, e0, a1);
            a1 = fmaf(x1, e1, a1);
        }
        mxi[rr] = mx; s0[rr] = a0; s1[rr] = a1;
    }

#pragma unroll
    for (int rr = 0; rr < ROWSPB; rr++) {
#pragma unroll
        for (int o = 16; o > 0; o >>= 1) {
            mxi[rr] = max(mxi[rr], __shfl_xor_sync(0xffffffffu, mxi[rr], o));
            s0[rr] += __shfl_xor_sync(0xffffffffu, s0[rr], o);
            s1[rr] += __shfl_xor_sync(0xffffffffu, s1[rr], o);
        }
        if (lane == 0) { sm0[rr][warp] = s0[rr]; sm1[rr][warp] = s1[rr]; smm[rr][warp] = mxi[rr]; }
    }
    if (tid < ROWSPB) scnt[tid] = 0;
    __syncthreads();

    // ---- phase B: warps 0..ROWSPB-1 finalize one row each (lanes 0..7)
    if (warp < ROWSPB && lane < 8) {
        int rr = warp;
        float a0 = sm0[rr][lane];
        float a1 = sm1[rr][lane];
        int   mx = smm[rr][lane];
#pragma unroll
        for (int o = 4; o > 0; o >>= 1) {
            a0 += __shfl_xor_sync(0xffu, a0, o, 8);
            a1 += __shfl_xor_sync(0xffu, a1, o, 8);
            mx = max(mx, __shfl_xor_sync(0xffu, mx, o, 8));
        }
        if (lane == 0) {
            int row = r0 + rr;
            float c0 = logf(a0);
            g_c0[row] = c0;
            g_mp[row] = 0.f;
            g_rowent[row] = c0 - a1 / a0;
            sfin[rr] = mx;
        }
    }
    __syncthreads();

    // ---- phase C: integer candidate scan
#pragma unroll
    for (int rr = 0; rr < ROWSPB; rr++) {
        int thr = sfin[rr] - MARGIN_INT;
#pragma unroll
        for (int j = 0; j < 8; j++) {
            unsigned int lvp = __vadd2(acc[rr][j], biasq[j]);
            int lo = (int)(lvp & 0xffffu);
            int hi = (int)(lvp >> 16);
            if (lo >= thr) {
                int ix = atomicAdd(&scnt[rr], 1);
                if (ix < MAXC) scand[rr][ix] = tb16 + 2 * j;
            }
            if (hi >= thr) {
                int ix = atomicAdd(&scnt[rr], 1);
                if (ix < MAXC) scand[rr][ix] = tb16 + 2 * j + 1;
            }
        }
    }
    __syncthreads();

    if (tid < ROWSPB) g_cnt[r0 + tid] = scnt[tid];
    if (tid < ROWSPB * MAXC) {
        int rr = tid >> 4, sl = tid & 15;
        int n = scnt[rr] < MAXC ? scnt[rr] : MAXC;
        g_cand[r0 + rr][sl] = (sl < n) ? scand[rr][sl] : 0;
    }
}

// ---------------------------------------------------------------------------
__device__ __forceinline__ float exact_logit(const float* __restrict__ bias,
                                             const float* __restrict__ W,
                                             const int* toks, int t) {
    float l = __ldg(&bias[t]);
#pragma unroll
    for (int k = 0; k < FW; k++)
        if (toks[k] >= 0)
            l += __ldg(&W[(size_t)t * CDIM + toks[k] * 5 + k]);
    return l;
}

// ---------------------------------------------------------------------------
// Combine: 8 lanes/row; exact fp32 recheck of candidates.
// ---------------------------------------------------------------------------
__global__ __launch_bounds__(256) void combine_k(const float* __restrict__ bias,
                                                 const int* __restrict__ sent,
                                                 const float* __restrict__ W,
                                                 float* __restrict__ out) {
    int tid = threadIdx.x;
    int row = blockIdx.x * 32 + (tid >> 3);
    int lane8 = tid & 7;
    int bb = row >> 9, s = row & 511;

    int rawn = g_cnt[row];
    int nc = rawn < MAXC ? rawn : MAXC;
    float mp = g_mp[row], c0 = g_c0[row];
    int clamped = g_clamped;

    int toks[FW];
#pragma unroll
    for (int k = 0; k < FW; k++) {
        int p = s + k - 2;
        toks[k] = (p >= 0 && p < SLEN) ? __ldg(&sent[(bb << 9) + p]) : -1;
    }

    float le[2]; int te[2];
#pragma unroll
    for (int i = 0; i < 2; i++) {
        int ci = lane8 + 8 * i;
        if (ci < nc) { te[i] = g_cand[row][ci]; le[i] = exact_logit(bias, W, toks, te[i]); }
        else         { te[i] = 0x7fffffff;      le[i] = -1e30f; }
    }

    float m = fmaxf(le[0], le[1]);
#pragma unroll
    for (int o = 4; o > 0; o >>= 1)
        m = fmaxf(m, __shfl_xor_sync(0xffffffffu, m, o, 8));
    float cc = c0 + (mp - m);

    float blp = -1e30f; int bt = 0x7fffffff;
    int near = 0;
#pragma unroll
    for (int i = 0; i < 2; i++) {
        if (te[i] != 0x7fffffff) {
            float lp = (le[i] - m) - cc;
            if (lp > blp || (lp == blp && te[i] < bt)) { blp = lp; bt = te[i]; }
            if (le[i] > m - TIE_EPS) near++;
        }
    }
#pragma unroll
    for (int o = 4; o > 0; o >>= 1) {
        float olp = __shfl_xor_sync(0xffffffffu, blp, o, 8);
        int   ot  = __shfl_xor_sync(0xffffffffu, bt,  o, 8);
        int   on  = __shfl_xor_sync(0xffffffffu, near, o, 8);
        if (olp > blp || (olp == blp && ot < bt)) { blp = olp; bt = ot; }
        near += on;
    }

    if (lane8 == 0) {
        out[row] = (float)bt;
        out[NROWS + row] = blp;
        if (near >= 2 || rawn > MAXC || clamped) {
            int ix = atomicAdd(&g_nflag, 1);
            g_flaglist[ix] = row;
        }
    }
}

// ---------------------------------------------------------------------------
// Exact fixup for flagged rows (full 4096 fp32 logits).
// ---------------------------------------------------------------------------
__global__ __launch_bounds__(256) void fixup_k(const float* __restrict__ bias,
                                               const int* __restrict__ sent,
                                               const float* __restrict__ W,
                                               float* __restrict__ out) {
    __shared__ float sv[256];
    __shared__ int   si[256];
    __shared__ float sb[1];
    int tid = threadIdx.x;
    int nf = g_nflag;

    for (int it = blockIdx.x; it < nf; it += gridDim.x) {
        int row = g_flaglist[it];
        int bb = row >> 9, s = row & 511;
        int toks[FW];
#pragma unroll
        for (int k = 0; k < FW; k++) {
            int p = s + k - 2;
            toks[k] = (p >= 0 && p < SLEN) ? __ldg(&sent[(bb << 9) + p]) : -1;
        }
        float lv[16];
        float vmax = -1e30f;
#pragma unroll
        for (int j = 0; j < 16; j++) {
            lv[j] = exact_logit(bias, W, toks, tid * 16 + j);
            vmax = fmaxf(vmax, lv[j]);
        }
        sv[tid] = vmax;
        __syncthreads();
#pragma unroll
        for (int off = 128; off > 0; off >>= 1) {
            if (tid < off) sv[tid] = fmaxf(sv[tid], sv[tid + off]);
            __syncthreads();
        }
        float m = sv[0];
        __syncthreads();

        float s0 = 0.f;
#pragma unroll
        for (int j = 0; j < 16; j++) s0 += expf(lv[j] - m);
        sv[tid] = s0;
        __syncthreads();
#pragma unroll
        for (int off = 128; off > 0; off >>= 1) {
            if (tid < off) sv[tid] += sv[tid + off];
            __syncthreads();
        }
        if (tid == 0) sb[0] = logf(sv[0]);
        __syncthreads();
        float c = sb[0];
        __syncthreads();

        float blp = -1e30f;
        int bt = 0;
#pragma unroll
        for (int j = 0; j < 16; j++) {
            float lp = (lv[j] - m) - c;
            if (lp > blp) { blp = lp; bt = tid * 16 + j; }
        }
        sv[tid] = blp; si[tid] = bt;
        __syncthreads();
#pragma unroll
        for (int off = 128; off > 0; off >>= 1) {
            if (tid < off) {
                float ov = sv[tid + off];
                int   oi = si[tid + off];
                if (ov > sv[tid] || (ov == sv[tid] && oi < si[tid])) {
                    sv[tid] = ov; si[tid] = oi;
                }
            }
            __syncthreads();
        }
        if (tid == 0) {
            out[row] = (float)si[0];
            out[NROWS + row] = sv[0];
        }
        __syncthreads();
    }
}

// ---------------------------------------------------------------------------
__global__ __launch_bounds__(256) void finalize_k(float* __restrict__ out) {
    __shared__ double sd[256];
    int tid = threadIdx.x;
    double a = 0.0;
    for (int i = tid; i < NROWS; i += 256) a += (double)g_rowent[i];
    sd[tid] = a;
    __syncthreads();
#pragma unroll
    for (int off = 128; off > 0; off >>= 1) {
        if (tid < off) sd[tid] += sd[tid + off];
        __syncthreads();
    }
    if (tid == 0)
        out[2 * NROWS] = (float)(sd[0] / ((double)NROWS * (double)T));
}

// ---------------------------------------------------------------------------
extern "C" void kernel_launch(void* const* d_in, const int* in_sizes, int n_in,
                              void* d_out, int out_size) {
    const float* W    = (const float*)d_in[0];
    const float* bias = (const float*)d_in[1];
    const int*   sent = (const int*)d_in[2];
    float* out = (float*)d_out;

    reset_k<<<1, 1>>>();                               // launch 1
    biasq_k<<<1, 256>>>(bias);                         // launch 2
    dim3 tb(32, 8);
    dim3 tg(CDIM / 32, T / 128);
    transpose_k<<<tg, tb>>>(W);                        // launch 3
    gather_k<<<NROWS / ROWSPB, 256>>>(sent);           // launch 4 (ncu capture slot)
    combine_k<<<NROWS / 32, 256>>>(bias, sent, W, out);
    fixup_k<<<128, 256>>>(bias, sent, W, out);
    finalize_k<<<1, 256>>>(out);
}

// round 13
// speedup vs baseline: 20.0718x; 1.1409x over previous
#include <cuda_runtime.h>
#include <cuda_fp16.h>

#define V 4096
#define T 4096
#define FW 5
#define BATCH 64
#define SLEN 512
#define NROWS (BATCH * SLEN)   // 32768
#define CDIM (V * FW)          // 20480
#define WMAX 0.06f
#define INVQ (127.0f / WMAX)
#define QUANT (WMAX / 127.0f)
#define QL (QUANT * 1.4426950408889634f)   // QUANT * log2(e)
#define MARGIN_INT 10
#define MAXC 16
#define TIE_EPS 4e-6f
#define ROWSPB 2

// u8 excess-128 transposed weights W8[k][v][t] -- 84 MB working set
__device__ unsigned char g_W8[(size_t)FW * V * T];
// bias quantized to the same grid, excess-1024, packed u16x2
__device__ unsigned int g_biasq[T / 2];
__device__ float g_c0[NROWS];
__device__ float g_mp[NROWS];
__device__ int   g_cnt[NROWS];
__device__ int   g_cand[NROWS][MAXC];
__device__ float g_rowent[NROWS];
__device__ int   g_flaglist[NROWS];
__device__ int   g_nflag;
__device__ int   g_clamped;

// ---------------------------------------------------------------------------
__global__ void reset_k() { g_nflag = 0; g_clamped = 0; }

// ---------------------------------------------------------------------------
__global__ __launch_bounds__(256) void biasq_k(const float* __restrict__ bias) {
    int tid = threadIdx.x;
#pragma unroll
    for (int j = 0; j < 8; j++) {
        int t = tid * 16 + 2 * j;
        int b0 = __float2int_rn(__ldg(&bias[t]) * INVQ) + 1024;
        int b1 = __float2int_rn(__ldg(&bias[t + 1]) * INVQ) + 1024;
        b0 = min(max(b0, 0), 4095);
        b1 = min(max(b1, 0), 4095);
        g_biasq[tid * 8 + j] = (unsigned int)b0 | ((unsigned int)b1 << 16);
    }
}

// ---------------------------------------------------------------------------
// Transpose v2: W[t][v][k] f32 -> W8[k][v][t] u8 excess-128.
// 128x128 tiles, float4 reads, quantize-before-smem, u32 tile [32][133],
// phase-2 4x4 byte transpose (PRMT), conflict-free LDS/STS by construction.
// grid (CDIM/128, T/128) = (160, 32), block 256.
// ---------------------------------------------------------------------------
__global__ __launch_bounds__(256) void transpose_k(const float* __restrict__ W) {
    __shared__ unsigned int tile[32][133];    // [cf][t], stride 133 (5 mod 32)
    int c0 = blockIdx.x << 7;
    int t0 = blockIdx.y << 7;
    int tid = threadIdx.x;
    int tx = tid & 31;          // cf (4-c group)
    int ty = tid >> 5;          // 0..7

    bool clamp = false;
#pragma unroll
    for (int j = 0; j < 16; j++) {
        int r = j * 8 + ty;     // t offset 0..127
        float4 w4 = ((const float4*)(W + (size_t)(t0 + r) * CDIM + c0))[tx];
        int q0 = __float2int_rn(w4.x * INVQ);
        int q1 = __float2int_rn(w4.y * INVQ);
        int q2 = __float2int_rn(w4.z * INVQ);
        int q3 = __float2int_rn(w4.w * INVQ);
        clamp |= (max(max(abs(q0), abs(q1)), max(abs(q2), abs(q3))) > 127);
        q0 = min(max(q0, -127), 127) + 128;
        q1 = min(max(q1, -127), 127) + 128;
        q2 = min(max(q2, -127), 127) + 128;
        q3 = min(max(q3, -127), 127) + 128;
        tile[tx][r] = (unsigned int)q0 | ((unsigned int)q1 << 8) |
                      ((unsigned int)q2 << 16) | ((unsigned int)q3 << 24);
    }
    if (clamp) atomicExch(&g_clamped, 1);
    __syncthreads();

    int w = tid >> 5;           // warp 0..7
    int l = tid & 31;
    int lq = l & 3;             // cf sub-index
    int lt = l >> 2;            // tc sub-index 0..7
    int cf = w * 4 + lq;        // 0..31
#pragma unroll
    for (int i = 0; i < 4; i++) {
        int tc = i * 8 + lt;    // 0..31 (t-chunk of 4)
        unsigned int in0 = tile[cf][4 * tc + 0];
        unsigned int in1 = tile[cf][4 * tc + 1];
        unsigned int in2 = tile[cf][4 * tc + 2];
        unsigned int in3 = tile[cf][4 * tc + 3];
#pragma unroll
        for (int j = 0; j < 4; j++) {
            unsigned int sel = (unsigned int)j | ((unsigned int)(4 + j) << 4);
            unsigned int t01 = __byte_perm(in0, in1, sel);
            unsigned int t23 = __byte_perm(in2, in3, sel);
            unsigned int out = __byte_perm(t01, t23, 0x5410);
            int c = c0 + 4 * cf + j;
            int v = c / 5;
            int k = c - 5 * v;
            *(unsigned int*)(g_W8 + ((size_t)k * V + v) * T + t0 + 4 * tc) = out;
        }
    }
}

// ---------------------------------------------------------------------------
__device__ __forceinline__ void acc_u16(unsigned int* a, uint4 w) {
    const unsigned int* wu = (const unsigned int*)&w;
#pragma unroll
    for (int q = 0; q < 4; q++) {
        a[2 * q + 0] += __byte_perm(wu[q], 0, 0x4140);
        a[2 * q + 1] += __byte_perm(wu[q], 0, 0x4342);
    }
}

// ---------------------------------------------------------------------------
// Gather v3: 2 rows/block, 16 t/thread. Bias pre-added into integer acc;
// f16x2 exp (1 MUFU / 2 elements); fused candidate scan (rescan only
// threads whose local max clears the threshold).
// ---------------------------------------------------------------------------
__global__ __launch_bounds__(256, 4) void gather_k(const int* __restrict__ sent) {
    int r0 = blockIdx.x * ROWSPB;
    int bb = r0 >> 9;
    int s0r = r0 & 511;
    int tid = threadIdx.x;
    int lane = tid & 31, warp = tid >> 5;
    int tb16 = tid * 16;

    __shared__ float sm0[ROWSPB][8];
    __shared__ float sm1[ROWSPB][8];
    __shared__ int   smm[ROWSPB][8];
    __shared__ int   sfin[ROWSPB];
    __shared__ int   scand[ROWSPB][MAXC];
    __shared__ int   scnt[ROWSPB];

    // bias (integer grid) -- front-loaded so LDGs batch with weight loads
    uint4 bql = ((const uint4*)(g_biasq + tid * 8))[0];
    uint4 bqh = ((const uint4*)(g_biasq + tid * 8))[1];
    unsigned int bj[8] = {bql.x, bql.y, bql.z, bql.w, bqh.x, bqh.y, bqh.z, bqh.w};

    unsigned int acc[ROWSPB][8];
#pragma unroll
    for (int rr = 0; rr < ROWSPB; rr++)
#pragma unroll
        for (int j = 0; j < 8; j++) acc[rr][j] = 0;
    int nvalid[ROWSPB];

    const unsigned char* wb = g_W8 + tb16;

    if (s0r >= 2 && s0r + ROWSPB + 1 <= SLEN) {
        // fast path (s0r even, so worst p = s0r+1+2 <= 511)
        int toks[ROWSPB + 4];
#pragma unroll
        for (int i = 0; i < ROWSPB + 4; i++)
            toks[i] = __ldg(&sent[(bb << 9) + s0r - 2 + i]);
#pragma unroll
        for (int rr = 0; rr < ROWSPB; rr++) nvalid[rr] = FW;

#pragma unroll
        for (int k = 0; k < FW; k++) {
            uint4 w[ROWSPB];
#pragma unroll
            for (int rr = 0; rr < ROWSPB; rr++)
                w[rr] = *(const uint4*)(wb + ((size_t)k * V + toks[k + rr]) * T);
#pragma unroll
            for (int rr = 0; rr < ROWSPB; rr++)
                acc_u16(acc[rr], w[rr]);
        }
    } else {
#pragma unroll
        for (int rr = 0; rr < ROWSPB; rr++) nvalid[rr] = 0;
#pragma unroll
        for (int k = 0; k < FW; k++) {
#pragma unroll
            for (int rr = 0; rr < ROWSPB; rr++) {
                int p = s0r + rr + k - 2;
                if (p >= 0 && p < SLEN) {
                    nvalid[rr]++;
                    int tok = __ldg(&sent[(bb << 9) + p]);
                    uint4 w = *(const uint4*)(wb + ((size_t)k * V + tok) * T);
                    acc_u16(acc[rr], w);
                }
            }
        }
    }

    // pre-add bias: acc now holds integer logit n = m + 128*nvalid + 1024
#pragma unroll
    for (int rr = 0; rr < ROWSPB; rr++)
#pragma unroll
        for (int j = 0; j < 8; j++) acc[rr][j] = __vadd2(acc[rr][j], bj[j]);

    // ---- phase A: per-thread max + S0/S1 via f16x2 exp (no barriers)
    int   mxl[ROWSPB];
    float s0f[ROWSPB], s1f[ROWSPB];
#pragma unroll
    for (int rr = 0; rr < ROWSPB; rr++) {
        float fb = -(float)(128 * nvalid[rr] + 1024) * QL;
        unsigned int mx2 = 0;
        __half2 s0h = __float2half2_rn(0.f);
        __half2 s1h = __float2half2_rn(0.f);
#pragma unroll
        for (int j = 0; j < 8; j++) {
            unsigned int n = acc[rr][j];
            mx2 = __vmaxu2(mx2, n);
            int lo = (int)(n & 0xffffu);
            int hi = (int)(n >> 16);
            float y0 = fmaf((float)lo, QL, fb);   // x*log2(e)
            float y1 = fmaf((float)hi, QL, fb);
            unsigned int yh, eh;
            asm("cvt.rn.f16x2.f32 %0, %1, %2;" : "=r"(yh) : "f"(y1), "f"(y0));
            asm("ex2.approx.f16x2 %0, %1;" : "=r"(eh) : "r"(yh));
            __half2 yh2 = *(__half2*)&yh;
            __half2 eh2 = *(__half2*)&eh;
            s0h = __hadd2(s0h, eh2);
            s1h = __hfma2(yh2, eh2, s1h);
        }
        mxl[rr] = max((int)(mx2 & 0xffffu), (int)(mx2 >> 16));
        float2 f0 = __half22float2(s0h);
        float2 f1 = __half22float2(s1h);
        s0f[rr] = f0.x + f0.y;
        s1f[rr] = f1.x + f1.y;
    }

    // warp reduce
    int mxi[ROWSPB];
#pragma unroll
    for (int rr = 0; rr < ROWSPB; rr++) {
        mxi[rr] = mxl[rr];
#pragma unroll
        for (int o = 16; o > 0; o >>= 1) {
            mxi[rr] = max(mxi[rr], __shfl_xor_sync(0xffffffffu, mxi[rr], o));
            s0f[rr] += __shfl_xor_sync(0xffffffffu, s0f[rr], o);
            s1f[rr] += __shfl_xor_sync(0xffffffffu, s1f[rr], o);
        }
        if (lane == 0) { sm0[rr][warp] = s0f[rr]; sm1[rr][warp] = s1f[rr]; smm[rr][warp] = mxi[rr]; }
    }
    if (tid < ROWSPB) scnt[tid] = 0;
    __syncthreads();

    // ---- phase B: warps 0..ROWSPB-1 finalize one row each (lanes 0..7)
    if (warp < ROWSPB && lane < 8) {
        int rr = warp;
        float a0 = sm0[rr][lane];
        float a1 = sm1[rr][lane];
        int   mx = smm[rr][lane];
#pragma unroll
        for (int o = 4; o > 0; o >>= 1) {
            a0 += __shfl_xor_sync(0xffu, a0, o, 8);
            a1 += __shfl_xor_sync(0xffu, a1, o, 8);
            mx = max(mx, __shfl_xor_sync(0xffu, mx, o, 8));
        }
        if (lane == 0) {
            int row = r0 + rr;
            float c0 = logf(a0);
            g_c0[row] = c0;
            g_mp[row] = 0.f;                           // shift-free reference
            g_rowent[row] = c0 - (a1 * 0.6931471805599453f) / a0;  // S1 = a1*ln2
            sfin[rr] = mx;
        }
    }
    __syncthreads();

    // ---- phase C (fused): rescan only if this thread's local max qualifies
#pragma unroll
    for (int rr = 0; rr < ROWSPB; rr++) {
        int thr = sfin[rr] - MARGIN_INT;
        if (mxl[rr] >= thr) {
#pragma unroll
            for (int j = 0; j < 8; j++) {
                unsigned int n = acc[rr][j];
                int lo = (int)(n & 0xffffu);
                int hi = (int)(n >> 16);
                if (lo >= thr) {
                    int ix = atomicAdd(&scnt[rr], 1);
                    if (ix < MAXC) scand[rr][ix] = tb16 + 2 * j;
                }
                if (hi >= thr) {
                    int ix = atomicAdd(&scnt[rr], 1);
                    if (ix < MAXC) scand[rr][ix] = tb16 + 2 * j + 1;
                }
            }
        }
    }
    __syncthreads();

    if (tid < ROWSPB) g_cnt[r0 + tid] = scnt[tid];
    if (tid < ROWSPB * MAXC) {
        int rr = tid >> 4, sl = tid & 15;
        int n = scnt[rr] < MAXC ? scnt[rr] : MAXC;
        g_cand[r0 + rr][sl] = (sl < n) ? scand[rr][sl] : 0;
    }
}

// ---------------------------------------------------------------------------
__device__ __forceinline__ float exact_logit(const float* __restrict__ bias,
                                             const float* __restrict__ W,
                                             const int* toks, int t) {
    float l = __ldg(&bias[t]);
#pragma unroll
    for (int k = 0; k < FW; k++)
        if (toks[k] >= 0)
            l += __ldg(&W[(size_t)t * CDIM + toks[k] * 5 + k]);
    return l;
}

// ---------------------------------------------------------------------------
// Combine: 8 lanes/row; exact fp32 recheck of candidates.
// ---------------------------------------------------------------------------
__global__ __launch_bounds__(256) void combine_k(const float* __restrict__ bias,
                                                 const int* __restrict__ sent,
                                                 const float* __restrict__ W,
                                                 float* __restrict__ out) {
    int tid = threadIdx.x;
    int row = blockIdx.x * 32 + (tid >> 3);
    int lane8 = tid & 7;
    int bb = row >> 9, s = row & 511;

    int rawn = g_cnt[row];
    int nc = rawn < MAXC ? rawn : MAXC;
    float mp = g_mp[row], c0 = g_c0[row];
    int clamped = g_clamped;

    int toks[FW];
#pragma unroll
    for (int k = 0; k < FW; k++) {
        int p = s + k - 2;
        toks[k] = (p >= 0 && p < SLEN) ? __ldg(&sent[(bb << 9) + p]) : -1;
    }

    float le[2]; int te[2];
#pragma unroll
    for (int i = 0; i < 2; i++) {
        int ci = lane8 + 8 * i;
        if (ci < nc) { te[i] = g_cand[row][ci]; le[i] = exact_logit(bias, W, toks, te[i]); }
        else         { te[i] = 0x7fffffff;      le[i] = -1e30f; }
    }

    float m = fmaxf(le[0], le[1]);
#pragma unroll
    for (int o = 4; o > 0; o >>= 1)
        m = fmaxf(m, __shfl_xor_sync(0xffffffffu, m, o, 8));
    float cc = c0 + (mp - m);

    float blp = -1e30f; int bt = 0x7fffffff;
    int near = 0;
#pragma unroll
    for (int i = 0; i < 2; i++) {
        if (te[i] != 0x7fffffff) {
            float lp = (le[i] - m) - cc;
            if (lp > blp || (lp == blp && te[i] < bt)) { blp = lp; bt = te[i]; }
            if (le[i] > m - TIE_EPS) near++;
        }
    }
#pragma unroll
    for (int o = 4; o > 0; o >>= 1) {
        float olp = __shfl_xor_sync(0xffffffffu, blp, o, 8);
        int   ot  = __shfl_xor_sync(0xffffffffu, bt,  o, 8);
        int   on  = __shfl_xor_sync(0xffffffffu, near, o, 8);
        if (olp > blp || (olp == blp && ot < bt)) { blp = olp; bt = ot; }
        near += on;
    }

    if (lane8 == 0) {
        out[row] = (float)bt;
        out[NROWS + row] = blp;
        if (near >= 2 || rawn > MAXC || clamped) {
            int ix = atomicAdd(&g_nflag, 1);
            g_flaglist[ix] = row;
        }
    }
}

// ---------------------------------------------------------------------------
// Exact fixup for flagged rows (full 4096 fp32 logits).
// ---------------------------------------------------------------------------
__global__ __launch_bounds__(256) void fixup_k(const float* __restrict__ bias,
                                               const int* __restrict__ sent,
                                               const float* __restrict__ W,
                                               float* __restrict__ out) {
    __shared__ float sv[256];
    __shared__ int   si[256];
    __shared__ float sb[1];
    int tid = threadIdx.x;
    int nf = g_nflag;

    for (int it = blockIdx.x; it < nf; it += gridDim.x) {
        int row = g_flaglist[it];
        int bb = row >> 9, s = row & 511;
        int toks[FW];
#pragma unroll
        for (int k = 0; k < FW; k++) {
            int p = s + k - 2;
            toks[k] = (p >= 0 && p < SLEN) ? __ldg(&sent[(bb << 9) + p]) : -1;
        }
        float lv[16];
        float vmax = -1e30f;
#pragma unroll
        for (int j = 0; j < 16; j++) {
            lv[j] = exact_logit(bias, W, toks, tid * 16 + j);
            vmax = fmaxf(vmax, lv[j]);
        }
        sv[tid] = vmax;
        __syncthreads();
#pragma unroll
        for (int off = 128; off > 0; off >>= 1) {
            if (tid < off) sv[tid] = fmaxf(sv[tid], sv[tid + off]);
            __syncthreads();
        }
        float m = sv[0];
        __syncthreads();

        float s0 = 0.f;
#pragma unroll
        for (int j = 0; j < 16; j++) s0 += expf(lv[j] - m);
        sv[tid] = s0;
        __syncthreads();
#pragma unroll
        for (int off = 128; off > 0; off >>= 1) {
            if (tid < off) sv[tid] += sv[tid + off];
            __syncthreads();
        }
        if (tid == 0) sb[0] = logf(sv[0]);
        __syncthreads();
        float c = sb[0];
        __syncthreads();

        float blp = -1e30f;
        int bt = 0;
#pragma unroll
        for (int j = 0; j < 16; j++) {
            float lp = (lv[j] - m) - c;
            if (lp > blp) { blp = lp; bt = tid * 16 + j; }
        }
        sv[tid] = blp; si[tid] = bt;
        __syncthreads();
#pragma unroll
        for (int off = 128; off > 0; off >>= 1) {
            if (tid < off) {
                float ov = sv[tid + off];
                int   oi = si[tid + off];
                if (ov > sv[tid] || (ov == sv[tid] && oi < si[tid])) {
                    sv[tid] = ov; si[tid] = oi;
                }
            }
            __syncthreads();
        }
        if (tid == 0) {
            out[row] = (float)si[0];
            out[NROWS + row] = sv[0];
        }
        __syncthreads();
    }
}

// ---------------------------------------------------------------------------
__global__ __launch_bounds__(256) void finalize_k(float* __restrict__ out) {
    __shared__ double sd[256];
    int tid = threadIdx.x;
    double a = 0.0;
    for (int i = tid; i < NROWS; i += 256) a += (double)g_rowent[i];
    sd[tid] = a;
    __syncthreads();
#pragma unroll
    for (int off = 128; off > 0; off >>= 1) {
        if (tid < off) sd[tid] += sd[tid + off];
        __syncthreads();
    }
    if (tid == 0)
        out[2 * NROWS] = (float)(sd[0] / ((double)NROWS * (double)T));
}

// ---------------------------------------------------------------------------
extern "C" void kernel_launch(void* const* d_in, const int* in_sizes, int n_in,
                              void* d_out, int out_size) {
    const float* W    = (const float*)d_in[0];
    const float* bias = (const float*)d_in[1];
    const int*   sent = (const int*)d_in[2];
    float* out = (float*)d_out;

    reset_k<<<1, 1>>>();                               // launch 1
    biasq_k<<<1, 256>>>(bias);                         // launch 2
    dim3 tg(CDIM / 128, T / 128);
    transpose_k<<<tg, 256>>>(W);                       // launch 3
    gather_k<<<NROWS / ROWSPB, 256>>>(sent);           // launch 4 (ncu capture slot)
    combine_k<<<NROWS / 32, 256>>>(bias, sent, W, out);
    fixup_k<<<128, 256>>>(bias, sent, W, out);
    finalize_k<<<1, 256>>>(out);
}